// round 13
// baseline (speedup 1.0000x reference)
#include <cuda_runtime.h>
#include <mma.h>
#include <cstdint>

using namespace nvcuda;

#define NB  8
#define NS  4096
#define ND  1024
#define NA  64
#define NH  8
#define NHD 128
#define NBS (NB*NS)

// ---- scratch (static device globals: alloc-free per harness rules) ----
__device__ float g_logits[NBS*128];         // padded logits, ld=128
__device__ float g_hidden[NBS*ND];
__device__ float g_rw[NBS*NA];
__device__ float g_anchors[NB*NA*ND];
__device__ float g_qkv[NB*NA*3*ND];
__device__ float g_ctx[NB*NA*ND];
__device__ float g_mixed[NB*NA*ND];
__device__ float g_h[NBS*ND];
__device__ float g_t[134217728];            // FFN intermediate [NBS,4*ND]
__device__ float g_f[NBS*ND];
__device__ float g_uvec[ND];
__device__ float g_bvec[ND];
// tf32-pre-rounded operands
__device__ float g_xr[NBS*ND];
__device__ float g_w1r[ND*ND];
__device__ float g_w2p[ND*128];             // padded+rounded rm_w2, ld=128
__device__ float g_b2p[128];                // padded rm_b2
__device__ float g_inr[ND*3*ND];
__device__ float g_owr[ND*ND];
__device__ float g_f1r[(long)ND*4*ND];
__device__ float g_f2r[(long)4*ND*ND];

// ---- cp.async helpers ----
__device__ __forceinline__ void cp16(void* smem_dst, const void* gsrc) {
    uint32_t s = (uint32_t)__cvta_generic_to_shared(smem_dst);
    asm volatile("cp.async.cg.shared.global [%0], [%1], 16;\n" :: "r"(s), "l"(gsrc));
}
__device__ __forceinline__ void cp_commit() {
    asm volatile("cp.async.commit_group;\n");
}
template<int N> __device__ __forceinline__ void cp_wait() {
    asm volatile("cp.async.wait_group %0;\n" :: "n"(N));
}

__device__ __forceinline__ float rtf(float v) { return wmma::__float_to_tf32(v); }

// ---- elementwise tf32 RN rounding pass ----
__global__ void roundtf(const float4* __restrict__ src, float4* __restrict__ dst, long n4)
{
    long i = (long)blockIdx.x * blockDim.x + threadIdx.x;
    if (i >= n4) return;
    float4 v = src[i];
    v.x = rtf(v.x); v.y = rtf(v.y); v.z = rtf(v.z); v.w = rtf(v.w);
    dst[i] = v;
}

// ---- pad rm_w2 [1024,64] -> [1024,128] (round + zero-pad); pad rm_b2 ----
__global__ void pad_w2(const float* __restrict__ w2, const float* __restrict__ b2)
{
    int i = blockIdx.x * blockDim.x + threadIdx.x;      // 0..131071
    int j = i >> 7, c = i & 127;
    g_w2p[i] = (c < NA) ? rtf(w2[j * NA + c]) : 0.0f;
    if (i < 128) g_b2p[i] = (i < NA) ? b2[i] : 0.0f;
}

// ============================================================
// gemm_v2: C[M,N] = A[M,K] @ B[K,N] (+bias)(+rowscale*coladd)(relu)
// CTA tile 128x128, 128 threads = 4 warps (2x2), each 64x64.
// BK=32, 3-stage cp.async pipeline, 106KB smem -> 2 CTAs/SM.
// R13: explicit fragment double-buffering across ks steps
// (af/bf ping-pong; ~222 regs, under the 254 cap).
// Pre-rounded tf32 inputs; no in-loop cvt.
// ============================================================
#define V2_A (128*36)
#define V2_B (32*132)
#define V2_STG (V2_A + V2_B)          // 8832 floats per stage
#define V2_SMEM (3*V2_STG*4)          // 105984 bytes

template<bool RELU>
__global__ void __launch_bounds__(128, 2)
gemm_v2(const float* __restrict__ Ag, const float* __restrict__ Bg,
        const float* __restrict__ bias, const float* __restrict__ rowscale,
        const float* __restrict__ coladd, float* __restrict__ Cg,
        int M, int N, int K, int lda, int ldb, int ldc,
        long strideA, long strideB, long strideC)
{
    extern __shared__ float smemf[];
    const float* A = Ag + blockIdx.z * strideA;
    const float* B = Bg + blockIdx.z * strideB;
    float*       C = Cg + blockIdx.z * strideC;

    const int bm = blockIdx.y * 128;
    const int bn = blockIdx.x * 128;
    const int tid = threadIdx.x;
    const int warp = tid >> 5;
    const int wm = (warp >> 1) * 64;   // 0,64
    const int wn = (warp & 1) * 64;    // 0,64

    wmma::fragment<wmma::accumulator, 16,16,8, float> cf[4][4];
    #pragma unroll
    for (int i = 0; i < 4; i++)
        #pragma unroll
        for (int j = 0; j < 4; j++) wmma::fill_fragment(cf[i][j], 0.0f);

    // load mapping (float4 granularity, 128 threads)
    const int ar = tid >> 3, ac = tid & 7;     // A: 8 iters rows ar+i*16
    const int br = tid >> 5, bc = tid & 31;    // B: 8 iters rows br+i*4

    auto issue = [&](int k0, int st) {
        float* sA = smemf + st * V2_STG;
        float* sB = sA + V2_A;
        #pragma unroll
        for (int i = 0; i < 8; i++) {
            int m = ar + i * 16;
            cp16(&sA[m*36 + ac*4], &A[(long)(bm + m) * lda + k0 + ac*4]);
        }
        #pragma unroll
        for (int i = 0; i < 8; i++) {
            int k = br + i * 4;
            cp16(&sB[k*132 + bc*4], &B[(long)(k0 + k) * ldb + bn + bc*4]);
        }
    };

    const int nIter = K >> 5;
    issue(0, 0); cp_commit();
    if (nIter > 1) { issue(32, 1); cp_commit(); }

    // double-buffered fragments
    wmma::fragment<wmma::matrix_a,16,16,8,wmma::precision::tf32,wmma::row_major> af[2][4];
    wmma::fragment<wmma::matrix_b,16,16,8,wmma::precision::tf32,wmma::row_major> bf[2][4];

    for (int it = 0; it < nIter; it++) {
        if (it + 1 < nIter) cp_wait<1>(); else cp_wait<0>();
        __syncthreads();

        int jn = it + 2;
        if (jn < nIter) { issue(jn << 5, jn % 3); cp_commit(); }

        const float* cA = smemf + (it % 3) * V2_STG;
        const float* cB = cA + V2_A;

        // preload ks=0 fragments
        #pragma unroll
        for (int i = 0; i < 4; i++)
            wmma::load_matrix_sync(af[0][i], &cA[(wm + i*16)*36], 36);
        #pragma unroll
        for (int j = 0; j < 4; j++)
            wmma::load_matrix_sync(bf[0][j], &cB[wn + j*16], 132);

        #pragma unroll
        for (int ks = 0; ks < 4; ks++) {
            int cur = ks & 1, nxt = cur ^ 1;
            if (ks < 3) {
                #pragma unroll
                for (int i = 0; i < 4; i++)
                    wmma::load_matrix_sync(af[nxt][i], &cA[(wm + i*16)*36 + (ks+1)*8], 36);
                #pragma unroll
                for (int j = 0; j < 4; j++)
                    wmma::load_matrix_sync(bf[nxt][j], &cB[(ks+1)*8*132 + wn + j*16], 132);
            }
            #pragma unroll
            for (int i = 0; i < 4; i++)
                #pragma unroll
                for (int j = 0; j < 4; j++)
                    wmma::mma_sync(cf[i][j], af[cur][i], bf[cur][j], cf[i][j]);
        }
    }

    __syncthreads();
    float* sC = smemf;                       // 128*132*4 = 67.6KB <= 106KB
    #pragma unroll
    for (int i = 0; i < 4; i++)
        #pragma unroll
        for (int j = 0; j < 4; j++)
            wmma::store_matrix_sync(&sC[(wm + i*16)*132 + wn + j*16], cf[i][j], 132,
                                    wmma::mem_row_major);
    __syncthreads();

    #pragma unroll
    for (int i = 0; i < 32; i++) {
        int idx = tid + i * 128;              // 4096 float4 over 128x128
        int r = idx >> 5, cv = idx & 31;
        float4 v = *(const float4*)&sC[r*132 + cv*4];
        int grow = bm + r, gc = bn + cv*4;
        if (bias) {
            v.x += bias[gc+0]; v.y += bias[gc+1]; v.z += bias[gc+2]; v.w += bias[gc+3];
        }
        if (rowscale) {
            float rs = rowscale[grow];
            v.x += rs * coladd[gc+0]; v.y += rs * coladd[gc+1];
            v.z += rs * coladd[gc+2]; v.w += rs * coladd[gc+3];
        }
        if (RELU) {
            v.x = fmaxf(v.x, 0.f); v.y = fmaxf(v.y, 0.f);
            v.z = fmaxf(v.z, 0.f); v.w = fmaxf(v.w, 0.f);
        }
        v.x = rtf(v.x); v.y = rtf(v.y); v.z = rtf(v.z); v.w = rtf(v.w);
        *(float4*)&C[(long)grow * ldc + gc] = v;
    }
}

// ============================================================
// gemm64: small/odd shapes (TRANS_A). Pre-rounded inputs.
// ============================================================
template<bool TRANS_A, bool RELU>
__global__ void gemm64(const float* __restrict__ Ag, const float* __restrict__ Bg,
                       const float* __restrict__ bias, const float* __restrict__ rowscale,
                       const float* __restrict__ coladd, float* __restrict__ Cg,
                       int M, int N, int K, int lda, int ldb, int ldc,
                       long strideA, long strideB, long strideC)
{
    constexpr int BM = 64, BN = 64, BK = 32;
    __shared__ __align__(32) float sA[BM*36];
    __shared__ __align__(32) float sB[BK*68];
    __shared__ __align__(32) float sC[64*68];

    const float* A = Ag + blockIdx.z * strideA;
    const float* B = Bg + blockIdx.z * strideB;
    float*       C = Cg + blockIdx.z * strideC;

    const int bm = blockIdx.y * BM;
    const int bn = blockIdx.x * BN;
    const int tid  = threadIdx.x;
    const int warp = tid >> 5;
    const int wm = (warp >> 1) * 32;
    const int wn = (warp & 1) * 32;

    wmma::fragment<wmma::accumulator, 16,16,8, float> cf[2][2];
    #pragma unroll
    for (int i = 0; i < 2; i++)
        #pragma unroll
        for (int j = 0; j < 2; j++) wmma::fill_fragment(cf[i][j], 0.0f);

    for (int k0 = 0; k0 < K; k0 += BK) {
        #pragma unroll
        for (int it = 0; it < 16; it++) {
            int idx = tid + it * 128;
            if (!TRANS_A) {
                int m = idx >> 5, k = idx & 31;
                sA[m*36 + k] = A[(long)(bm + m) * lda + (k0 + k)];
            } else {
                int m = idx & 63, k = idx >> 6;
                sA[m*36 + k] = A[(long)(k0 + k) * lda + (bm + m)];
            }
        }
        #pragma unroll
        for (int it = 0; it < 16; it++) {
            int idx = tid + it * 128;
            int n = idx & 63, k = idx >> 6;
            sB[k*68 + n] = B[(long)(k0 + k) * ldb + (bn + n)];
        }
        __syncthreads();

        #pragma unroll
        for (int ks = 0; ks < 4; ks++) {
            wmma::fragment<wmma::matrix_a,16,16,8,wmma::precision::tf32,wmma::row_major> af[2];
            wmma::fragment<wmma::matrix_b,16,16,8,wmma::precision::tf32,wmma::row_major> bf[2];
            #pragma unroll
            for (int i = 0; i < 2; i++)
                wmma::load_matrix_sync(af[i], &sA[(wm + i*16)*36 + ks*8], 36);
            #pragma unroll
            for (int j = 0; j < 2; j++)
                wmma::load_matrix_sync(bf[j], &sB[(ks*8)*68 + wn + j*16], 68);
            #pragma unroll
            for (int i = 0; i < 2; i++)
                #pragma unroll
                for (int j = 0; j < 2; j++)
                    wmma::mma_sync(cf[i][j], af[i], bf[j], cf[i][j]);
        }
        __syncthreads();
    }

    #pragma unroll
    for (int i = 0; i < 2; i++)
        #pragma unroll
        for (int j = 0; j < 2; j++)
            wmma::store_matrix_sync(&sC[(wm + i*16)*68 + wn + j*16], cf[i][j], 68,
                                    wmma::mem_row_major);
    __syncthreads();

    #pragma unroll
    for (int it = 0; it < 32; it++) {
        int idx = tid + it * 128;
        int r = idx >> 6, c = idx & 63;
        float v = sC[r*68 + c];
        int grow = bm + r, gcol = bn + c;
        if (bias)     v += bias[gcol];
        if (rowscale) v += rowscale[grow] * coladd[gcol];
        if (RELU)     v = fmaxf(v, 0.0f);
        C[(long)grow * ldc + gcol] = rtf(v);
    }
}

// ---- fold energy path ----
__global__ void prep_uv(const float* __restrict__ rm_w1, const float* __restrict__ rm_b1,
                        const float* __restrict__ ep_w, const float* __restrict__ ep_b)
{
    int j = blockIdx.x * blockDim.x + threadIdx.x;
    if (j >= ND) return;
    float u = 0.f, v = 0.f;
    #pragma unroll 8
    for (int a = 0; a < NA; a++) {
        float w = rm_w1[(long)(ND + a) * ND + j];
        u += ep_w[a] * w;
        v += ep_b[a] * w;
    }
    g_uvec[j] = u;
    g_bvec[j] = v + rm_b1[j];
}

// ---- softmax over A=64; reads padded logits (ld=128), tf32-rounded rw ----
__global__ void softmax64()
{
    int row  = blockIdx.x * 8 + (threadIdx.x >> 5);
    int lane = threadIdx.x & 31;
    const float* lr = g_logits + (long)row * 128;
    float v0 = lr[lane], v1 = lr[lane + 32];
    float m = fmaxf(v0, v1);
    #pragma unroll
    for (int o = 16; o > 0; o >>= 1) m = fmaxf(m, __shfl_xor_sync(0xffffffffu, m, o));
    v0 = expf(v0 - m); v1 = expf(v1 - m);
    float s = v0 + v1;
    #pragma unroll
    for (int o = 16; o > 0; o >>= 1) s += __shfl_xor_sync(0xffffffffu, s, o);
    float inv = 1.0f / s;
    float* rw = g_rw + (long)row * 64;
    rw[lane] = rtf(v0 * inv); rw[lane + 32] = rtf(v1 * inv);
}

// ---- anchor self-attention; outputs tf32-rounded ctx ----
__global__ void attn_kernel()
{
    int h = blockIdx.x, b = blockIdx.y;
    const float* base = g_qkv + (long)b * NA * 3 * ND;
    __shared__ float sc[64*64];
    int tid = threadIdx.x;
    const float scale = 0.08838834764831845f;

    #pragma unroll
    for (int it = 0; it < 16; it++) {
        int idx = tid + it * 256;
        int i = idx >> 6, j = idx & 63;
        const float* q = base + (long)i * 3 * ND + h * NHD;
        const float* k = base + (long)j * 3 * ND + ND + h * NHD;
        float acc = 0.f;
        #pragma unroll 8
        for (int d = 0; d < NHD; d++) acc += q[d] * k[d];
        sc[i*64 + j] = acc * scale;
    }
    __syncthreads();

    int warp = tid >> 5, lane = tid & 31;
    for (int r = warp; r < 64; r += 8) {
        float v0 = sc[r*64 + lane], v1 = sc[r*64 + lane + 32];
        float m = fmaxf(v0, v1);
        #pragma unroll
        for (int o = 16; o > 0; o >>= 1) m = fmaxf(m, __shfl_xor_sync(0xffffffffu, m, o));
        v0 = expf(v0 - m); v1 = expf(v1 - m);
        float s = v0 + v1;
        #pragma unroll
        for (int o = 16; o > 0; o >>= 1) s += __shfl_xor_sync(0xffffffffu, s, o);
        float inv = 1.0f / s;
        sc[r*64 + lane] = v0 * inv; sc[r*64 + lane + 32] = v1 * inv;
    }
    __syncthreads();

    #pragma unroll
    for (int it = 0; it < 32; it++) {
        int idx = tid + it * 256;
        int i = idx >> 7, d = idx & 127;
        const float* v = base + 2 * ND + h * NHD + d;
        float acc = 0.f;
        #pragma unroll 8
        for (int j = 0; j < 64; j++) acc += sc[i*64 + j] * v[(long)j * 3 * ND];
        g_ctx[((long)b * NA + i) * ND + h * NHD + d] = rtf(acc);
    }
}

__device__ __forceinline__ float blockReduceSum(float v)
{
    __shared__ float sh[9];
    __syncthreads();
    int lane = threadIdx.x & 31, warp = threadIdx.x >> 5;
    #pragma unroll
    for (int o = 16; o > 0; o >>= 1) v += __shfl_xor_sync(0xffffffffu, v, o);
    if (lane == 0) sh[warp] = v;
    __syncthreads();
    if (warp == 0) {
        float t = (lane < 8) ? sh[lane] : 0.f;
        #pragma unroll
        for (int o = 4; o > 0; o >>= 1) t += __shfl_xor_sync(0xffffffffu, t, o);
        if (lane == 0) sh[8] = t;
    }
    __syncthreads();
    return sh[8];
}

// ---- out = LayerNorm(X + Y) * g + b ; round_out: tf32-round result ----
__global__ void add_ln(const float* __restrict__ X, const float* __restrict__ Y,
                       const float* __restrict__ gam, const float* __restrict__ bet,
                       float* __restrict__ out, int round_out)
{
    long row = blockIdx.x;
    int tid = threadIdx.x;
    float vals[4];
    float s = 0.f;
    #pragma unroll
    for (int i = 0; i < 4; i++) {
        int d = tid + i * 256;
        float v = X[row * ND + d] + Y[row * ND + d];
        vals[i] = v; s += v;
    }
    float mean = blockReduceSum(s) * (1.0f / ND);
    float vs = 0.f;
    #pragma unroll
    for (int i = 0; i < 4; i++) { float t = vals[i] - mean; vs += t * t; }
    float var = blockReduceSum(vs) * (1.0f / ND);
    float inv = rsqrtf(var + 1e-5f);
    #pragma unroll
    for (int i = 0; i < 4; i++) {
        int d = tid + i * 256;
        float o = (vals[i] - mean) * inv * gam[d] + bet[d];
        out[row * ND + d] = round_out ? rtf(o) : o;
    }
}

// ============================================================
extern "C" void kernel_launch(void* const* d_in, const int* in_sizes, int n_in,
                              void* d_out, int out_size)
{
    const float* x     = (const float*)d_in[0];
    const float* efas  = (const float*)d_in[1];
    const float* ep_w  = (const float*)d_in[2];
    const float* ep_b  = (const float*)d_in[3];
    const float* rm_w1 = (const float*)d_in[5];
    const float* rm_b1 = (const float*)d_in[6];
    const float* rm_w2 = (const float*)d_in[7];
    const float* rm_b2 = (const float*)d_in[8];
    const float* in_w  = (const float*)d_in[9];
    const float* in_b  = (const float*)d_in[10];
    const float* ow    = (const float*)d_in[11];
    const float* ob    = (const float*)d_in[12];
    const float* fw1   = (const float*)d_in[13];
    const float* fb1   = (const float*)d_in[14];
    const float* fw2   = (const float*)d_in[15];
    const float* fb2   = (const float*)d_in[16];
    const float* l1g   = (const float*)d_in[17];
    const float* l1b   = (const float*)d_in[18];
    const float* l2g   = (const float*)d_in[19];
    const float* l2b   = (const float*)d_in[20];
    float* out = (float*)d_out;

    float *p_hidden, *p_logits, *p_rw, *p_anchors, *p_qkv, *p_ctx, *p_mixed,
          *p_h, *p_t, *p_f, *p_u, *p_bv;
    float *p_xr, *p_w1r, *p_w2p, *p_b2p, *p_inr, *p_owr, *p_f1r, *p_f2r;
    cudaGetSymbolAddress((void**)&p_hidden,  g_hidden);
    cudaGetSymbolAddress((void**)&p_logits,  g_logits);
    cudaGetSymbolAddress((void**)&p_rw,      g_rw);
    cudaGetSymbolAddress((void**)&p_anchors, g_anchors);
    cudaGetSymbolAddress((void**)&p_qkv,     g_qkv);
    cudaGetSymbolAddress((void**)&p_ctx,     g_ctx);
    cudaGetSymbolAddress((void**)&p_mixed,   g_mixed);
    cudaGetSymbolAddress((void**)&p_h,       g_h);
    cudaGetSymbolAddress((void**)&p_t,       g_t);
    cudaGetSymbolAddress((void**)&p_f,       g_f);
    cudaGetSymbolAddress((void**)&p_u,       g_uvec);
    cudaGetSymbolAddress((void**)&p_bv,      g_bvec);
    cudaGetSymbolAddress((void**)&p_xr,      g_xr);
    cudaGetSymbolAddress((void**)&p_w1r,     g_w1r);
    cudaGetSymbolAddress((void**)&p_w2p,     g_w2p);
    cudaGetSymbolAddress((void**)&p_b2p,     g_b2p);
    cudaGetSymbolAddress((void**)&p_inr,     g_inr);
    cudaGetSymbolAddress((void**)&p_owr,     g_owr);
    cudaGetSymbolAddress((void**)&p_f1r,     g_f1r);
    cudaGetSymbolAddress((void**)&p_f2r,     g_f2r);

    static bool attr_set = false;
    if (!attr_set) {
        cudaFuncSetAttribute(gemm_v2<true>,  cudaFuncAttributeMaxDynamicSharedMemorySize, V2_SMEM);
        cudaFuncSetAttribute(gemm_v2<false>, cudaFuncAttributeMaxDynamicSharedMemorySize, V2_SMEM);
        attr_set = true;
    }

    dim3 blk64(128), blk128(128);
    auto rl = [](long n) { return (unsigned)((n/4 + 255) / 256); };

    // Launch order: hidden GEMM at index 3 (ncu profiles idx 3).
    prep_uv<<<4, 256>>>(rm_w1, rm_b1, ep_w, ep_b);                                             // 0
    roundtf<<<rl((long)NBS*ND), 256>>>((const float4*)x,    (float4*)p_xr,  (long)NBS*ND/4);   // 1
    roundtf<<<rl((long)ND*ND), 256>>>((const float4*)rm_w1, (float4*)p_w1r, (long)ND*ND/4);    // 2

    // 3) hidden = relu(xr@W1r + efas*u + bvec)    [32768,1024]x[1024,1024]  ← ncu target
    gemm_v2<true><<<dim3(ND/128, NBS/128), blk128, V2_SMEM>>>(
        p_xr, p_w1r, p_bv, efas, p_u, p_hidden, NBS, ND, ND, ND, ND, ND, 0, 0, 0);

    pad_w2<<<512, 256>>>(rm_w2, rm_b2);                                                        // 4
    roundtf<<<rl((long)ND*3*ND), 256>>>((const float4*)in_w, (float4*)p_inr, (long)ND*3*ND/4); // 5
    roundtf<<<rl((long)ND*ND), 256>>>((const float4*)ow,     (float4*)p_owr, (long)ND*ND/4);   // 6
    roundtf<<<rl((long)ND*4*ND), 256>>>((const float4*)fw1,  (float4*)p_f1r, (long)ND*4*ND/4); // 7
    roundtf<<<rl((long)4*ND*ND), 256>>>((const float4*)fw2,  (float4*)p_f2r, (long)4*ND*ND/4); // 8

    // logits(padded N=128) = hidden @ w2p + b2p   [32768,1024]x[1024,128]
    gemm_v2<false><<<dim3(1, NBS/128), blk128, V2_SMEM>>>(
        p_hidden, p_w2p, p_b2p, nullptr, nullptr, p_logits, NBS, 128, ND, ND, 128, 128, 0, 0, 0);

    softmax64<<<NBS/8, 256>>>();

    // anchors[b] = rw[b]^T @ xr[b]                batched
    gemm64<true, false><<<dim3(ND/64, 1, NB), blk64>>>(
        p_rw, p_xr, nullptr, nullptr, nullptr, p_anchors, NA, ND, NS,
        NA, ND, ND, (long)NS*NA, (long)NS*ND, (long)NA*ND);

    // qkv = anchors @ inr + in_b                  [512,1024]x[1024,3072]
    gemm_v2<false><<<dim3(3*ND/128, NB*NA/128), blk128, V2_SMEM>>>(
        p_anchors, p_inr, in_b, nullptr, nullptr, p_qkv, NB*NA, 3*ND, ND, ND, 3*ND, 3*ND, 0, 0, 0);

    attn_kernel<<<dim3(NH, NB), 256>>>();

    // mixed = ctx @ owr + ob                      [512,1024]x[1024,1024]
    gemm_v2<false><<<dim3(ND/128, NB*NA/128), blk128, V2_SMEM>>>(
        p_ctx, p_owr, ob, nullptr, nullptr, p_mixed, NB*NA, ND, ND, ND, ND, ND, 0, 0, 0);

    // token_updates[b] = rw[b] @ mixed[b]         [4096,64]x[64,1024], batched
    gemm_v2<false><<<dim3(ND/128, NS/128, NB), blk128, V2_SMEM>>>(
        p_rw, p_mixed, nullptr, nullptr, nullptr, p_f, NS, ND, NA,
        NA, ND, ND, (long)NS*NA, (long)NA*ND, (long)NS*ND);

    // h = LN1(x + token_updates)  (tf32-rounded: feeds ffn1 GEMM)
    add_ln<<<NBS, 256>>>(x, p_f, l1g, l1b, p_h, 1);

    // t = relu(h @ f1r + fb1)                     [32768,1024]x[1024,4096]
    gemm_v2<true><<<dim3(4*ND/128, NBS/128), blk128, V2_SMEM>>>(
        p_h, p_f1r, fb1, nullptr, nullptr, p_t, NBS, 4*ND, ND, ND, 4*ND, 4*ND, 0, 0, 0);

    // f = t @ f2r + fb2                           [32768,4096]x[4096,1024]
    gemm_v2<false><<<dim3(ND/128, NBS/128), blk128, V2_SMEM>>>(
        p_t, p_f2r, fb2, nullptr, nullptr, p_f, NBS, ND, 4*ND, 4*ND, ND, ND, 0, 0, 0);

    // out = LN2(h + f)  (full precision)
    add_ln<<<NBS, 256>>>(p_h, p_f, l2g, l2b, out, 0);
}

// round 14
// speedup vs baseline: 1.1129x; 1.1129x over previous
#include <cuda_runtime.h>
#include <cuda_bf16.h>
#include <mma.h>
#include <cstdint>

using namespace nvcuda;

#define NB  8
#define NS  4096
#define ND  1024
#define NA  64
#define NH  8
#define NHD 128
#define NBS (NB*NS)

// ---- scratch (static device globals: alloc-free per harness rules) ----
__device__ float g_logits[NBS*128];         // padded logits, ld=128
__device__ float g_hidden[NBS*ND];
__device__ float g_rw[NBS*NA];
__device__ float g_anchors[NB*NA*ND];
__device__ float g_qkv[NB*NA*3*ND];
__device__ float g_ctx[NB*NA*ND];
__device__ float g_mixed[NB*NA*ND];
__device__ float g_h[NBS*ND];
__device__ float g_t[134217728];            // FFN intermediate [NBS,4*ND]
__device__ float g_f[NBS*ND];
__device__ float g_uvec[ND];
__device__ float g_bvec[ND];
// tf32-pre-rounded operands
__device__ float g_xr[NBS*ND];
__device__ float g_w1r[ND*ND];
__device__ float g_w2p[ND*128];             // padded+rounded rm_w2, ld=128
__device__ float g_b2p[128];                // padded rm_b2
__device__ float g_inr[ND*3*ND];
__device__ float g_owr[ND*ND];
__device__ float g_f2r[(long)4*ND*ND];
// bf16 split operands (ffn1 experiment)
__device__ __nv_bfloat16 g_hhi[NBS*ND], g_hlo[NBS*ND];
__device__ __nv_bfloat16 g_f1hi[(long)ND*4*ND], g_f1lo[(long)ND*4*ND];

// ---- cp.async helpers ----
__device__ __forceinline__ void cp16(void* smem_dst, const void* gsrc) {
    uint32_t s = (uint32_t)__cvta_generic_to_shared(smem_dst);
    asm volatile("cp.async.cg.shared.global [%0], [%1], 16;\n" :: "r"(s), "l"(gsrc));
}
__device__ __forceinline__ void cp_commit() {
    asm volatile("cp.async.commit_group;\n");
}
template<int N> __device__ __forceinline__ void cp_wait() {
    asm volatile("cp.async.wait_group %0;\n" :: "n"(N));
}

__device__ __forceinline__ float rtf(float v) { return wmma::__float_to_tf32(v); }

// ---- elementwise tf32 RN rounding pass ----
__global__ void roundtf(const float4* __restrict__ src, float4* __restrict__ dst, long n4)
{
    long i = (long)blockIdx.x * blockDim.x + threadIdx.x;
    if (i >= n4) return;
    float4 v = src[i];
    v.x = rtf(v.x); v.y = rtf(v.y); v.z = rtf(v.z); v.w = rtf(v.w);
    dst[i] = v;
}

// ---- fp32 -> bf16 (hi, lo) split ----
__global__ void split_bf(const float* __restrict__ src,
                         __nv_bfloat16* __restrict__ hi, __nv_bfloat16* __restrict__ lo,
                         long n)
{
    long i = (long)blockIdx.x * blockDim.x + threadIdx.x;
    if (i >= n) return;
    float v = src[i];
    __nv_bfloat16 h = __float2bfloat16(v);
    hi[i] = h;
    lo[i] = __float2bfloat16(v - __bfloat162float(h));
}

// ---- pad rm_w2 [1024,64] -> [1024,128] (round + zero-pad); pad rm_b2 ----
__global__ void pad_w2(const float* __restrict__ w2, const float* __restrict__ b2)
{
    int i = blockIdx.x * blockDim.x + threadIdx.x;      // 0..131071
    int j = i >> 7, c = i & 127;
    g_w2p[i] = (c < NA) ? rtf(w2[j * NA + c]) : 0.0f;
    if (i < 128) g_b2p[i] = (i < NA) ? b2[i] : 0.0f;
}

// ============================================================
// gemm_v2 (tf32, best known): unchanged from R12.
// ============================================================
#define V2_A (128*36)
#define V2_B (32*132)
#define V2_STG (V2_A + V2_B)
#define V2_SMEM (3*V2_STG*4)

template<bool RELU>
__global__ void __launch_bounds__(128, 2)
gemm_v2(const float* __restrict__ Ag, const float* __restrict__ Bg,
        const float* __restrict__ bias, const float* __restrict__ rowscale,
        const float* __restrict__ coladd, float* __restrict__ Cg,
        int M, int N, int K, int lda, int ldb, int ldc,
        long strideA, long strideB, long strideC)
{
    extern __shared__ float smemf[];
    const float* A = Ag + blockIdx.z * strideA;
    const float* B = Bg + blockIdx.z * strideB;
    float*       C = Cg + blockIdx.z * strideC;

    const int bm = blockIdx.y * 128;
    const int bn = blockIdx.x * 128;
    const int tid = threadIdx.x;
    const int warp = tid >> 5;
    const int wm = (warp >> 1) * 64;
    const int wn = (warp & 1) * 64;

    wmma::fragment<wmma::accumulator, 16,16,8, float> cf[4][4];
    #pragma unroll
    for (int i = 0; i < 4; i++)
        #pragma unroll
        for (int j = 0; j < 4; j++) wmma::fill_fragment(cf[i][j], 0.0f);

    const int ar = tid >> 3, ac = tid & 7;
    const int br = tid >> 5, bc = tid & 31;

    auto issue = [&](int k0, int st) {
        float* sA = smemf + st * V2_STG;
        float* sB = sA + V2_A;
        #pragma unroll
        for (int i = 0; i < 8; i++) {
            int m = ar + i * 16;
            cp16(&sA[m*36 + ac*4], &A[(long)(bm + m) * lda + k0 + ac*4]);
        }
        #pragma unroll
        for (int i = 0; i < 8; i++) {
            int k = br + i * 4;
            cp16(&sB[k*132 + bc*4], &B[(long)(k0 + k) * ldb + bn + bc*4]);
        }
    };

    const int nIter = K >> 5;
    issue(0, 0); cp_commit();
    if (nIter > 1) { issue(32, 1); cp_commit(); }

    for (int it = 0; it < nIter; it++) {
        if (it + 1 < nIter) cp_wait<1>(); else cp_wait<0>();
        __syncthreads();

        int jn = it + 2;
        if (jn < nIter) { issue(jn << 5, jn % 3); cp_commit(); }

        const float* cA = smemf + (it % 3) * V2_STG;
        const float* cB = cA + V2_A;
        #pragma unroll
        for (int ks = 0; ks < 4; ks++) {
            wmma::fragment<wmma::matrix_a,16,16,8,wmma::precision::tf32,wmma::row_major> af[4];
            wmma::fragment<wmma::matrix_b,16,16,8,wmma::precision::tf32,wmma::row_major> bf[4];
            #pragma unroll
            for (int i = 0; i < 4; i++)
                wmma::load_matrix_sync(af[i], &cA[(wm + i*16)*36 + ks*8], 36);
            #pragma unroll
            for (int j = 0; j < 4; j++)
                wmma::load_matrix_sync(bf[j], &cB[(ks*8)*132 + wn + j*16], 132);
            #pragma unroll
            for (int i = 0; i < 4; i++)
                #pragma unroll
                for (int j = 0; j < 4; j++)
                    wmma::mma_sync(cf[i][j], af[i], bf[j], cf[i][j]);
        }
    }

    __syncthreads();
    float* sC = smemf;
    #pragma unroll
    for (int i = 0; i < 4; i++)
        #pragma unroll
        for (int j = 0; j < 4; j++)
            wmma::store_matrix_sync(&sC[(wm + i*16)*132 + wn + j*16], cf[i][j], 132,
                                    wmma::mem_row_major);
    __syncthreads();

    #pragma unroll
    for (int i = 0; i < 32; i++) {
        int idx = tid + i * 128;
        int r = idx >> 5, cv = idx & 31;
        float4 v = *(const float4*)&sC[r*132 + cv*4];
        int grow = bm + r, gc = bn + cv*4;
        if (bias) {
            v.x += bias[gc+0]; v.y += bias[gc+1]; v.z += bias[gc+2]; v.w += bias[gc+3];
        }
        if (rowscale) {
            float rs = rowscale[grow];
            v.x += rs * coladd[gc+0]; v.y += rs * coladd[gc+1];
            v.z += rs * coladd[gc+2]; v.w += rs * coladd[gc+3];
        }
        if (RELU) {
            v.x = fmaxf(v.x, 0.f); v.y = fmaxf(v.y, 0.f);
            v.z = fmaxf(v.z, 0.f); v.w = fmaxf(v.w, 0.f);
        }
        v.x = rtf(v.x); v.y = rtf(v.y); v.z = rtf(v.z); v.w = rtf(v.w);
        *(float4*)&C[(long)grow * ldc + gc] = v;
    }
}

// ============================================================
// gemm_bf16s: C[M,N] = (Ahi+Alo)@(Bhi+Blo) + bias (relu, tf32-rounded out)
// bf16 2-way split, 3 MMAs per product term (drop lo*lo), fp32 accum.
// CTA 128x128, 128 threads = 4 warps (2x2), each 64x64.
// BK=32 (2 ks steps of k16). 3-stage cp.async, ~111KB smem -> 2 CTAs/SM.
// A: [M,K] bf16 row-major; B: [K,N] bf16 row-major.
// ============================================================
#define BF_AH (128*40)                     // halves, ld=40 (32 data + 8 pad)
#define BF_BH (32*136)                     // halves, ld=136
#define BF_STG (2*BF_AH + 2*BF_BH)         // halves per stage = 18944
#define BF_SMEM (3*BF_STG*2)               // 113664 bytes

template<bool RELU>
__global__ void __launch_bounds__(128, 2)
gemm_bf16s(const __nv_bfloat16* __restrict__ Ahi, const __nv_bfloat16* __restrict__ Alo,
           const __nv_bfloat16* __restrict__ Bhi, const __nv_bfloat16* __restrict__ Blo,
           const float* __restrict__ bias, float* __restrict__ Cg,
           int M, int N, int K)
{
    extern __shared__ __nv_bfloat16 smemh[];
    const int bm = blockIdx.y * 128;
    const int bn = blockIdx.x * 128;
    const int tid = threadIdx.x;
    const int warp = tid >> 5;
    const int wm = (warp >> 1) * 64;
    const int wn = (warp & 1) * 64;

    wmma::fragment<wmma::accumulator, 16,16,16, float> cf[4][4];
    #pragma unroll
    for (int i = 0; i < 4; i++)
        #pragma unroll
        for (int j = 0; j < 4; j++) wmma::fill_fragment(cf[i][j], 0.0f);

    // load maps (cp16 = 8 halves). A: 512 cp16/buffer, B: 512 cp16/buffer.
    const int am = tid >> 2, ak = tid & 3;     // A: m = am + i*32, chunk ak (8 halves)
    const int bk = tid >> 4, bn8 = tid & 15;   // B: k = bk + i*8,  chunk bn8

    auto issue = [&](int k0, int st) {
        __nv_bfloat16* sAh = smemh + st * BF_STG;
        __nv_bfloat16* sAl = sAh + BF_AH;
        __nv_bfloat16* sBh = sAl + BF_AH;
        __nv_bfloat16* sBl = sBh + BF_BH;
        #pragma unroll
        for (int i = 0; i < 4; i++) {
            int m = am + i * 32;
            long go = (long)(bm + m) * K + k0 + ak * 8;
            cp16(&sAh[m*40 + ak*8], Ahi + go);
            cp16(&sAl[m*40 + ak*8], Alo + go);
        }
        #pragma unroll
        for (int i = 0; i < 4; i++) {
            int k = bk + i * 8;
            long go = (long)(k0 + k) * N + bn + bn8 * 8;
            cp16(&sBh[k*136 + bn8*8], Bhi + go);
            cp16(&sBl[k*136 + bn8*8], Blo + go);
        }
    };

    const int nIter = K >> 5;
    issue(0, 0); cp_commit();
    if (nIter > 1) { issue(32, 1); cp_commit(); }

    for (int it = 0; it < nIter; it++) {
        if (it + 1 < nIter) cp_wait<1>(); else cp_wait<0>();
        __syncthreads();

        int jn = it + 2;
        if (jn < nIter) { issue(jn << 5, jn % 3); cp_commit(); }

        const __nv_bfloat16* cAh = smemh + (it % 3) * BF_STG;
        const __nv_bfloat16* cAl = cAh + BF_AH;
        const __nv_bfloat16* cBh = cAl + BF_AH;
        const __nv_bfloat16* cBl = cBh + BF_BH;

        #pragma unroll
        for (int ks = 0; ks < 2; ks++) {       // 2 x k16
            wmma::fragment<wmma::matrix_a,16,16,16,__nv_bfloat16,wmma::row_major> ah[4], al[4];
            wmma::fragment<wmma::matrix_b,16,16,16,__nv_bfloat16,wmma::row_major> bh[4], bl[4];
            #pragma unroll
            for (int i = 0; i < 4; i++) {
                wmma::load_matrix_sync(ah[i], &cAh[(wm + i*16)*40 + ks*16], 40);
                wmma::load_matrix_sync(al[i], &cAl[(wm + i*16)*40 + ks*16], 40);
            }
            #pragma unroll
            for (int j = 0; j < 4; j++) {
                wmma::load_matrix_sync(bh[j], &cBh[(ks*16)*136 + wn + j*16], 136);
                wmma::load_matrix_sync(bl[j], &cBl[(ks*16)*136 + wn + j*16], 136);
            }
            #pragma unroll
            for (int i = 0; i < 4; i++)
                #pragma unroll
                for (int j = 0; j < 4; j++) {
                    wmma::mma_sync(cf[i][j], ah[i], bh[j], cf[i][j]);
                    wmma::mma_sync(cf[i][j], ah[i], bl[j], cf[i][j]);
                    wmma::mma_sync(cf[i][j], al[i], bh[j], cf[i][j]);
                }
        }
    }

    __syncthreads();
    float* sC = (float*)smemh;                 // 128*132*4 = 67.6KB <= 111KB
    #pragma unroll
    for (int i = 0; i < 4; i++)
        #pragma unroll
        for (int j = 0; j < 4; j++)
            wmma::store_matrix_sync(&sC[(wm + i*16)*132 + wn + j*16], cf[i][j], 132,
                                    wmma::mem_row_major);
    __syncthreads();

    #pragma unroll
    for (int i = 0; i < 32; i++) {
        int idx = tid + i * 128;
        int r = idx >> 5, cv = idx & 31;
        float4 v = *(const float4*)&sC[r*132 + cv*4];
        int grow = bm + r, gc = bn + cv*4;
        if (bias) {
            v.x += bias[gc+0]; v.y += bias[gc+1]; v.z += bias[gc+2]; v.w += bias[gc+3];
        }
        if (RELU) {
            v.x = fmaxf(v.x, 0.f); v.y = fmaxf(v.y, 0.f);
            v.z = fmaxf(v.z, 0.f); v.w = fmaxf(v.w, 0.f);
        }
        v.x = rtf(v.x); v.y = rtf(v.y); v.z = rtf(v.z); v.w = rtf(v.w);
        *(float4*)&Cg[(long)grow * N + gc] = v;
    }
}

// ============================================================
// gemm64: small/odd shapes (TRANS_A). Pre-rounded inputs.
// ============================================================
template<bool TRANS_A, bool RELU>
__global__ void gemm64(const float* __restrict__ Ag, const float* __restrict__ Bg,
                       const float* __restrict__ bias, const float* __restrict__ rowscale,
                       const float* __restrict__ coladd, float* __restrict__ Cg,
                       int M, int N, int K, int lda, int ldb, int ldc,
                       long strideA, long strideB, long strideC)
{
    constexpr int BM = 64, BN = 64, BK = 32;
    __shared__ __align__(32) float sA[BM*36];
    __shared__ __align__(32) float sB[BK*68];
    __shared__ __align__(32) float sC[64*68];

    const float* A = Ag + blockIdx.z * strideA;
    const float* B = Bg + blockIdx.z * strideB;
    float*       C = Cg + blockIdx.z * strideC;

    const int bm = blockIdx.y * BM;
    const int bn = blockIdx.x * BN;
    const int tid  = threadIdx.x;
    const int warp = tid >> 5;
    const int wm = (warp >> 1) * 32;
    const int wn = (warp & 1) * 32;

    wmma::fragment<wmma::accumulator, 16,16,8, float> cf[2][2];
    #pragma unroll
    for (int i = 0; i < 2; i++)
        #pragma unroll
        for (int j = 0; j < 2; j++) wmma::fill_fragment(cf[i][j], 0.0f);

    for (int k0 = 0; k0 < K; k0 += BK) {
        #pragma unroll
        for (int it = 0; it < 16; it++) {
            int idx = tid + it * 128;
            if (!TRANS_A) {
                int m = idx >> 5, k = idx & 31;
                sA[m*36 + k] = A[(long)(bm + m) * lda + (k0 + k)];
            } else {
                int m = idx & 63, k = idx >> 6;
                sA[m*36 + k] = A[(long)(k0 + k) * lda + (bm + m)];
            }
        }
        #pragma unroll
        for (int it = 0; it < 16; it++) {
            int idx = tid + it * 128;
            int n = idx & 63, k = idx >> 6;
            sB[k*68 + n] = B[(long)(k0 + k) * ldb + (bn + n)];
        }
        __syncthreads();

        #pragma unroll
        for (int ks = 0; ks < 4; ks++) {
            wmma::fragment<wmma::matrix_a,16,16,8,wmma::precision::tf32,wmma::row_major> af[2];
            wmma::fragment<wmma::matrix_b,16,16,8,wmma::precision::tf32,wmma::row_major> bf[2];
            #pragma unroll
            for (int i = 0; i < 2; i++)
                wmma::load_matrix_sync(af[i], &sA[(wm + i*16)*36 + ks*8], 36);
            #pragma unroll
            for (int j = 0; j < 2; j++)
                wmma::load_matrix_sync(bf[j], &sB[(ks*8)*68 + wn + j*16], 68);
            #pragma unroll
            for (int i = 0; i < 2; i++)
                #pragma unroll
                for (int j = 0; j < 2; j++)
                    wmma::mma_sync(cf[i][j], af[i], bf[j], cf[i][j]);
        }
        __syncthreads();
    }

    #pragma unroll
    for (int i = 0; i < 2; i++)
        #pragma unroll
        for (int j = 0; j < 2; j++)
            wmma::store_matrix_sync(&sC[(wm + i*16)*68 + wn + j*16], cf[i][j], 68,
                                    wmma::mem_row_major);
    __syncthreads();

    #pragma unroll
    for (int it = 0; it < 32; it++) {
        int idx = tid + it * 128;
        int r = idx >> 6, c = idx & 63;
        float v = sC[r*68 + c];
        int grow = bm + r, gcol = bn + c;
        if (bias)     v += bias[gcol];
        if (rowscale) v += rowscale[grow] * coladd[gcol];
        if (RELU)     v = fmaxf(v, 0.0f);
        C[(long)grow * ldc + gcol] = rtf(v);
    }
}

// ---- fold energy path ----
__global__ void prep_uv(const float* __restrict__ rm_w1, const float* __restrict__ rm_b1,
                        const float* __restrict__ ep_w, const float* __restrict__ ep_b)
{
    int j = blockIdx.x * blockDim.x + threadIdx.x;
    if (j >= ND) return;
    float u = 0.f, v = 0.f;
    #pragma unroll 8
    for (int a = 0; a < NA; a++) {
        float w = rm_w1[(long)(ND + a) * ND + j];
        u += ep_w[a] * w;
        v += ep_b[a] * w;
    }
    g_uvec[j] = u;
    g_bvec[j] = v + rm_b1[j];
}

// ---- softmax over A=64; reads padded logits (ld=128), tf32-rounded rw ----
__global__ void softmax64()
{
    int row  = blockIdx.x * 8 + (threadIdx.x >> 5);
    int lane = threadIdx.x & 31;
    const float* lr = g_logits + (long)row * 128;
    float v0 = lr[lane], v1 = lr[lane + 32];
    float m = fmaxf(v0, v1);
    #pragma unroll
    for (int o = 16; o > 0; o >>= 1) m = fmaxf(m, __shfl_xor_sync(0xffffffffu, m, o));
    v0 = expf(v0 - m); v1 = expf(v1 - m);
    float s = v0 + v1;
    #pragma unroll
    for (int o = 16; o > 0; o >>= 1) s += __shfl_xor_sync(0xffffffffu, s, o);
    float inv = 1.0f / s;
    float* rw = g_rw + (long)row * 64;
    rw[lane] = rtf(v0 * inv); rw[lane + 32] = rtf(v1 * inv);
}

// ---- anchor self-attention; outputs tf32-rounded ctx ----
__global__ void attn_kernel()
{
    int h = blockIdx.x, b = blockIdx.y;
    const float* base = g_qkv + (long)b * NA * 3 * ND;
    __shared__ float sc[64*64];
    int tid = threadIdx.x;
    const float scale = 0.08838834764831845f;

    #pragma unroll
    for (int it = 0; it < 16; it++) {
        int idx = tid + it * 256;
        int i = idx >> 6, j = idx & 63;
        const float* q = base + (long)i * 3 * ND + h * NHD;
        const float* k = base + (long)j * 3 * ND + ND + h * NHD;
        float acc = 0.f;
        #pragma unroll 8
        for (int d = 0; d < NHD; d++) acc += q[d] * k[d];
        sc[i*64 + j] = acc * scale;
    }
    __syncthreads();

    int warp = tid >> 5, lane = tid & 31;
    for (int r = warp; r < 64; r += 8) {
        float v0 = sc[r*64 + lane], v1 = sc[r*64 + lane + 32];
        float m = fmaxf(v0, v1);
        #pragma unroll
        for (int o = 16; o > 0; o >>= 1) m = fmaxf(m, __shfl_xor_sync(0xffffffffu, m, o));
        v0 = expf(v0 - m); v1 = expf(v1 - m);
        float s = v0 + v1;
        #pragma unroll
        for (int o = 16; o > 0; o >>= 1) s += __shfl_xor_sync(0xffffffffu, s, o);
        float inv = 1.0f / s;
        sc[r*64 + lane] = v0 * inv; sc[r*64 + lane + 32] = v1 * inv;
    }
    __syncthreads();

    #pragma unroll
    for (int it = 0; it < 32; it++) {
        int idx = tid + it * 256;
        int i = idx >> 7, d = idx & 127;
        const float* v = base + 2 * ND + h * NHD + d;
        float acc = 0.f;
        #pragma unroll 8
        for (int j = 0; j < 64; j++) acc += sc[i*64 + j] * v[(long)j * 3 * ND];
        g_ctx[((long)b * NA + i) * ND + h * NHD + d] = rtf(acc);
    }
}

__device__ __forceinline__ float blockReduceSum(float v)
{
    __shared__ float sh[9];
    __syncthreads();
    int lane = threadIdx.x & 31, warp = threadIdx.x >> 5;
    #pragma unroll
    for (int o = 16; o > 0; o >>= 1) v += __shfl_xor_sync(0xffffffffu, v, o);
    if (lane == 0) sh[warp] = v;
    __syncthreads();
    if (warp == 0) {
        float t = (lane < 8) ? sh[lane] : 0.f;
        #pragma unroll
        for (int o = 4; o > 0; o >>= 1) t += __shfl_xor_sync(0xffffffffu, t, o);
        if (lane == 0) sh[8] = t;
    }
    __syncthreads();
    return sh[8];
}

// ---- out = LayerNorm(X + Y) * g + b ; optional bf16 split side-output ----
__global__ void add_ln(const float* __restrict__ X, const float* __restrict__ Y,
                       const float* __restrict__ gam, const float* __restrict__ bet,
                       float* __restrict__ out,
                       __nv_bfloat16* __restrict__ ohi, __nv_bfloat16* __restrict__ olo)
{
    long row = blockIdx.x;
    int tid = threadIdx.x;
    float vals[4];
    float s = 0.f;
    #pragma unroll
    for (int i = 0; i < 4; i++) {
        int d = tid + i * 256;
        float v = X[row * ND + d] + Y[row * ND + d];
        vals[i] = v; s += v;
    }
    float mean = blockReduceSum(s) * (1.0f / ND);
    float vs = 0.f;
    #pragma unroll
    for (int i = 0; i < 4; i++) { float t = vals[i] - mean; vs += t * t; }
    float var = blockReduceSum(vs) * (1.0f / ND);
    float inv = rsqrtf(var + 1e-5f);
    #pragma unroll
    for (int i = 0; i < 4; i++) {
        int d = tid + i * 256;
        float o = (vals[i] - mean) * inv * gam[d] + bet[d];
        out[row * ND + d] = o;
        if (ohi) {
            __nv_bfloat16 h = __float2bfloat16(o);
            ohi[row * ND + d] = h;
            olo[row * ND + d] = __float2bfloat16(o - __bfloat162float(h));
        }
    }
}

// ============================================================
extern "C" void kernel_launch(void* const* d_in, const int* in_sizes, int n_in,
                              void* d_out, int out_size)
{
    const float* x     = (const float*)d_in[0];
    const float* efas  = (const float*)d_in[1];
    const float* ep_w  = (const float*)d_in[2];
    const float* ep_b  = (const float*)d_in[3];
    const float* rm_w1 = (const float*)d_in[5];
    const float* rm_b1 = (const float*)d_in[6];
    const float* rm_w2 = (const float*)d_in[7];
    const float* rm_b2 = (const float*)d_in[8];
    const float* in_w  = (const float*)d_in[9];
    const float* in_b  = (const float*)d_in[10];
    const float* ow    = (const float*)d_in[11];
    const float* ob    = (const float*)d_in[12];
    const float* fw1   = (const float*)d_in[13];
    const float* fb1   = (const float*)d_in[14];
    const float* fw2   = (const float*)d_in[15];
    const float* fb2   = (const float*)d_in[16];
    const float* l1g   = (const float*)d_in[17];
    const float* l1b   = (const float*)d_in[18];
    const float* l2g   = (const float*)d_in[19];
    const float* l2b   = (const float*)d_in[20];
    float* out = (float*)d_out;

    float *p_hidden, *p_logits, *p_rw, *p_anchors, *p_qkv, *p_ctx, *p_mixed,
          *p_h, *p_t, *p_f, *p_u, *p_bv;
    float *p_xr, *p_w1r, *p_w2p, *p_b2p, *p_inr, *p_owr, *p_f2r;
    __nv_bfloat16 *p_hhi, *p_hlo, *p_f1hi, *p_f1lo;
    cudaGetSymbolAddress((void**)&p_hidden,  g_hidden);
    cudaGetSymbolAddress((void**)&p_logits,  g_logits);
    cudaGetSymbolAddress((void**)&p_rw,      g_rw);
    cudaGetSymbolAddress((void**)&p_anchors, g_anchors);
    cudaGetSymbolAddress((void**)&p_qkv,     g_qkv);
    cudaGetSymbolAddress((void**)&p_ctx,     g_ctx);
    cudaGetSymbolAddress((void**)&p_mixed,   g_mixed);
    cudaGetSymbolAddress((void**)&p_h,       g_h);
    cudaGetSymbolAddress((void**)&p_t,       g_t);
    cudaGetSymbolAddress((void**)&p_f,       g_f);
    cudaGetSymbolAddress((void**)&p_u,       g_uvec);
    cudaGetSymbolAddress((void**)&p_bv,      g_bvec);
    cudaGetSymbolAddress((void**)&p_xr,      g_xr);
    cudaGetSymbolAddress((void**)&p_w1r,     g_w1r);
    cudaGetSymbolAddress((void**)&p_w2p,     g_w2p);
    cudaGetSymbolAddress((void**)&p_b2p,     g_b2p);
    cudaGetSymbolAddress((void**)&p_inr,     g_inr);
    cudaGetSymbolAddress((void**)&p_owr,     g_owr);
    cudaGetSymbolAddress((void**)&p_f2r,     g_f2r);
    cudaGetSymbolAddress((void**)&p_hhi,     g_hhi);
    cudaGetSymbolAddress((void**)&p_hlo,     g_hlo);
    cudaGetSymbolAddress((void**)&p_f1hi,    g_f1hi);
    cudaGetSymbolAddress((void**)&p_f1lo,    g_f1lo);

    static bool attr_set = false;
    if (!attr_set) {
        cudaFuncSetAttribute(gemm_v2<true>,  cudaFuncAttributeMaxDynamicSharedMemorySize, V2_SMEM);
        cudaFuncSetAttribute(gemm_v2<false>, cudaFuncAttributeMaxDynamicSharedMemorySize, V2_SMEM);
        cudaFuncSetAttribute(gemm_bf16s<true>,  cudaFuncAttributeMaxDynamicSharedMemorySize, BF_SMEM);
        attr_set = true;
    }

    dim3 blk64(128), blk128(128);
    auto rl = [](long n) { return (unsigned)((n/4 + 255) / 256); };

    // Launch order: hidden GEMM at index 3 (ncu profiles idx 3).
    prep_uv<<<4, 256>>>(rm_w1, rm_b1, ep_w, ep_b);                                             // 0
    roundtf<<<rl((long)NBS*ND), 256>>>((const float4*)x,    (float4*)p_xr,  (long)NBS*ND/4);   // 1
    roundtf<<<rl((long)ND*ND), 256>>>((const float4*)rm_w1, (float4*)p_w1r, (long)ND*ND/4);    // 2

    // 3) hidden = relu(xr@W1r + efas*u + bvec)    [32768,1024]x[1024,1024]  ← ncu target
    gemm_v2<true><<<dim3(ND/128, NBS/128), blk128, V2_SMEM>>>(
        p_xr, p_w1r, p_bv, efas, p_u, p_hidden, NBS, ND, ND, ND, ND, ND, 0, 0, 0);

    pad_w2<<<512, 256>>>(rm_w2, rm_b2);
    roundtf<<<rl((long)ND*3*ND), 256>>>((const float4*)in_w, (float4*)p_inr, (long)ND*3*ND/4);
    roundtf<<<rl((long)ND*ND), 256>>>((const float4*)ow,     (float4*)p_owr, (long)ND*ND/4);
    split_bf<<<(unsigned)(((long)ND*4*ND + 255)/256), 256>>>(fw1, p_f1hi, p_f1lo, (long)ND*4*ND);
    roundtf<<<rl((long)4*ND*ND), 256>>>((const float4*)fw2,  (float4*)p_f2r, (long)4*ND*ND/4);

    // logits(padded N=128) = hidden @ w2p + b2p   [32768,1024]x[1024,128]
    gemm_v2<false><<<dim3(1, NBS/128), blk128, V2_SMEM>>>(
        p_hidden, p_w2p, p_b2p, nullptr, nullptr, p_logits, NBS, 128, ND, ND, 128, 128, 0, 0, 0);

    softmax64<<<NBS/8, 256>>>();

    // anchors[b] = rw[b]^T @ xr[b]                batched
    gemm64<true, false><<<dim3(ND/64, 1, NB), blk64>>>(
        p_rw, p_xr, nullptr, nullptr, nullptr, p_anchors, NA, ND, NS,
        NA, ND, ND, (long)NS*NA, (long)NS*ND, (long)NA*ND);

    // qkv = anchors @ inr + in_b                  [512,1024]x[1024,3072]
    gemm_v2<false><<<dim3(3*ND/128, NB*NA/128), blk128, V2_SMEM>>>(
        p_anchors, p_inr, in_b, nullptr, nullptr, p_qkv, NB*NA, 3*ND, ND, ND, 3*ND, 3*ND, 0, 0, 0);

    attn_kernel<<<dim3(NH, NB), 256>>>();

    // mixed = ctx @ owr + ob                      [512,1024]x[1024,1024]
    gemm_v2<false><<<dim3(ND/128, NB*NA/128), blk128, V2_SMEM>>>(
        p_ctx, p_owr, ob, nullptr, nullptr, p_mixed, NB*NA, ND, ND, ND, ND, ND, 0, 0, 0);

    // token_updates[b] = rw[b] @ mixed[b]         [4096,64]x[64,1024], batched
    gemm_v2<false><<<dim3(ND/128, NS/128, NB), blk128, V2_SMEM>>>(
        p_rw, p_mixed, nullptr, nullptr, nullptr, p_f, NS, ND, NA,
        NA, ND, ND, (long)NS*NA, (long)NA*ND, (long)NS*ND);

    // h = LN1(x + token_updates)  (fp32 for LN2 + bf16 hi/lo for ffn1)
    add_ln<<<NBS, 256>>>(x, p_f, l1g, l1b, p_h, p_hhi, p_hlo);

    // t = relu(h @ fw1 + fb1)   ← bf16-split EXPERIMENT  [32768,1024]x[1024,4096]
    gemm_bf16s<true><<<dim3(4*ND/128, NBS/128), blk128, BF_SMEM>>>(
        p_hhi, p_hlo, p_f1hi, p_f1lo, fb1, p_t, NBS, 4*ND, ND);

    // f = t @ f2r + fb2        ← tf32 control         [32768,4096]x[4096,1024]
    gemm_v2<false><<<dim3(ND/128, NBS/128), blk128, V2_SMEM>>>(
        p_t, p_f2r, fb2, nullptr, nullptr, p_f, NBS, ND, 4*ND, 4*ND, ND, ND, 0, 0, 0);

    // out = LN2(h + f)  (full precision)
    add_ln<<<NBS, 256>>>(p_h, p_f, l2g, l2b, out, nullptr, nullptr);
}

// round 16
// speedup vs baseline: 1.2781x; 1.1485x over previous
#include <cuda_runtime.h>
#include <cuda_bf16.h>
#include <mma.h>
#include <cstdint>

using namespace nvcuda;

#define NB  8
#define NS  4096
#define ND  1024
#define NA  64
#define NH  8
#define NHD 128
#define NBS (NB*NS)

// ---- scratch (static device globals: alloc-free per harness rules) ----
__device__ float g_logits[NBS*128];         // padded logits, ld=128
__device__ float g_rw[NBS*NA];
__device__ float g_anchors[NB*NA*ND];
__device__ float g_qkv[NB*NA*3*ND];
__device__ float g_ctx[NB*NA*ND];
__device__ float g_mixed[NB*NA*ND];
__device__ float g_h[NBS*ND];
__device__ float g_f[NBS*ND];
__device__ float g_uvec[ND];
__device__ float g_bvec[ND];
__device__ float g_b2p[128];                // padded rm_b2
// tf32-pre-rounded operands (medium GEMMs)
__device__ float g_xr[NBS*ND];
__device__ float g_inr[ND*3*ND];
__device__ float g_owr[ND*ND];
// bf16 split operands
__device__ __nv_bfloat16 g_xhi[NBS*ND],  g_xlo[NBS*ND];
__device__ __nv_bfloat16 g_w1hi[ND*ND],  g_w1lo[ND*ND];
__device__ __nv_bfloat16 g_hidhi[NBS*ND], g_hidlo[NBS*ND];
__device__ __nv_bfloat16 g_w2phi[ND*128], g_w2plo[ND*128];
__device__ __nv_bfloat16 g_hhi[NBS*ND],  g_hlo[NBS*ND];
__device__ __nv_bfloat16 g_f1hi[(long)ND*4*ND], g_f1lo[(long)ND*4*ND];
__device__ __nv_bfloat16 g_f2hi[(long)4*ND*ND], g_f2lo[(long)4*ND*ND];
__device__ __nv_bfloat16 g_thi[(long)NBS*4*ND], g_tlo[(long)NBS*4*ND];

// ---- cp.async helpers ----
__device__ __forceinline__ void cp16(void* smem_dst, const void* gsrc) {
    uint32_t s = (uint32_t)__cvta_generic_to_shared(smem_dst);
    asm volatile("cp.async.cg.shared.global [%0], [%1], 16;\n" :: "r"(s), "l"(gsrc));
}
__device__ __forceinline__ void cp_commit() {
    asm volatile("cp.async.commit_group;\n");
}
template<int N> __device__ __forceinline__ void cp_wait() {
    asm volatile("cp.async.wait_group %0;\n" :: "n"(N));
}

__device__ __forceinline__ float rtf(float v) { return wmma::__float_to_tf32(v); }

// ---- elementwise tf32 RN rounding pass ----
__global__ void roundtf(const float4* __restrict__ src, float4* __restrict__ dst, long n4)
{
    long i = (long)blockIdx.x * blockDim.x + threadIdx.x;
    if (i >= n4) return;
    float4 v = src[i];
    v.x = rtf(v.x); v.y = rtf(v.y); v.z = rtf(v.z); v.w = rtf(v.w);
    dst[i] = v;
}

// ---- fp32 -> bf16 (hi, lo) split ----
__global__ void split_bf(const float* __restrict__ src,
                         __nv_bfloat16* __restrict__ hi, __nv_bfloat16* __restrict__ lo,
                         long n)
{
    long i = (long)blockIdx.x * blockDim.x + threadIdx.x;
    if (i >= n) return;
    float v = src[i];
    __nv_bfloat16 h = __float2bfloat16(v);
    hi[i] = h;
    lo[i] = __float2bfloat16(v - __bfloat162float(h));
}

// ---- pad rm_w2 [1024,64] -> [1024,128] bf16 hi/lo; pad rm_b2 fp32 ----
__global__ void pad_w2_bf(const float* __restrict__ w2, const float* __restrict__ b2)
{
    int i = blockIdx.x * blockDim.x + threadIdx.x;      // 0..131071
    int j = i >> 7, c = i & 127;
    float v = (c < NA) ? w2[j * NA + c] : 0.0f;
    __nv_bfloat16 h = __float2bfloat16(v);
    g_w2phi[i] = h;
    g_w2plo[i] = __float2bfloat16(v - __bfloat162float(h));
    if (i < 128) g_b2p[i] = (i < NA) ? b2[i] : 0.0f;
}

// ============================================================
// gemm_bf16s: C[M,N] = (Ahi+Alo)@(Bhi+Blo) + bias (+rank1)(relu)
// bf16 2-way split, 3 MMAs per k16 step (drop lo*lo), fp32 accum.
// CTA 128x128, 128 threads = 4 warps (2x2), each 64x64.
// BK=32, 3-stage cp.async, ~111KB smem -> 2 CTAs/SM.
// SPLIT_OUT: write bf16 hi/lo; else fp32.
// ============================================================
#define BF_AH (128*40)
#define BF_BH (32*136)
#define BF_STG (2*BF_AH + 2*BF_BH)         // halves per stage
#define BF_SMEM (3*BF_STG*2)               // 113664 bytes

template<bool RELU, bool SPLIT_OUT, bool RANK1>
__global__ void __launch_bounds__(128, 2)
gemm_bf16s(const __nv_bfloat16* __restrict__ Ahi, const __nv_bfloat16* __restrict__ Alo,
           const __nv_bfloat16* __restrict__ Bhi, const __nv_bfloat16* __restrict__ Blo,
           const float* __restrict__ bias, const float* __restrict__ rowscale,
           const float* __restrict__ coladd,
           float* __restrict__ Cf, __nv_bfloat16* __restrict__ Chi,
           __nv_bfloat16* __restrict__ Clo,
           int M, int N, int K)
{
    extern __shared__ __nv_bfloat16 smemh[];
    const int bm = blockIdx.y * 128;
    const int bn = blockIdx.x * 128;
    const int tid = threadIdx.x;
    const int warp = tid >> 5;
    const int wm = (warp >> 1) * 64;
    const int wn = (warp & 1) * 64;

    wmma::fragment<wmma::accumulator, 16,16,16, float> cf[4][4];
    #pragma unroll
    for (int i = 0; i < 4; i++)
        #pragma unroll
        for (int j = 0; j < 4; j++) wmma::fill_fragment(cf[i][j], 0.0f);

    const int am = tid >> 2, ak = tid & 3;
    const int bk = tid >> 4, bn8 = tid & 15;

    auto issue = [&](int k0, int st) {
        __nv_bfloat16* sAh = smemh + st * BF_STG;
        __nv_bfloat16* sAl = sAh + BF_AH;
        __nv_bfloat16* sBh = sAl + BF_AH;
        __nv_bfloat16* sBl = sBh + BF_BH;
        #pragma unroll
        for (int i = 0; i < 4; i++) {
            int m = am + i * 32;
            long go = (long)(bm + m) * K + k0 + ak * 8;
            cp16(&sAh[m*40 + ak*8], Ahi + go);
            cp16(&sAl[m*40 + ak*8], Alo + go);
        }
        #pragma unroll
        for (int i = 0; i < 4; i++) {
            int k = bk + i * 8;
            long go = (long)(k0 + k) * N + bn + bn8 * 8;
            cp16(&sBh[k*136 + bn8*8], Bhi + go);
            cp16(&sBl[k*136 + bn8*8], Blo + go);
        }
    };

    const int nIter = K >> 5;
    issue(0, 0); cp_commit();
    if (nIter > 1) { issue(32, 1); cp_commit(); }

    for (int it = 0; it < nIter; it++) {
        if (it + 1 < nIter) cp_wait<1>(); else cp_wait<0>();
        __syncthreads();

        int jn = it + 2;
        if (jn < nIter) { issue(jn << 5, jn % 3); cp_commit(); }

        const __nv_bfloat16* cAh = smemh + (it % 3) * BF_STG;
        const __nv_bfloat16* cAl = cAh + BF_AH;
        const __nv_bfloat16* cBh = cAl + BF_AH;
        const __nv_bfloat16* cBl = cBh + BF_BH;

        #pragma unroll
        for (int ks = 0; ks < 2; ks++) {
            wmma::fragment<wmma::matrix_a,16,16,16,__nv_bfloat16,wmma::row_major> ah[4], al[4];
            wmma::fragment<wmma::matrix_b,16,16,16,__nv_bfloat16,wmma::row_major> bh[4], bl[4];
            #pragma unroll
            for (int i = 0; i < 4; i++) {
                wmma::load_matrix_sync(ah[i], &cAh[(wm + i*16)*40 + ks*16], 40);
                wmma::load_matrix_sync(al[i], &cAl[(wm + i*16)*40 + ks*16], 40);
            }
            #pragma unroll
            for (int j = 0; j < 4; j++) {
                wmma::load_matrix_sync(bh[j], &cBh[(ks*16)*136 + wn + j*16], 136);
                wmma::load_matrix_sync(bl[j], &cBl[(ks*16)*136 + wn + j*16], 136);
            }
            #pragma unroll
            for (int i = 0; i < 4; i++)
                #pragma unroll
                for (int j = 0; j < 4; j++) {
                    wmma::mma_sync(cf[i][j], ah[i], bh[j], cf[i][j]);
                    wmma::mma_sync(cf[i][j], ah[i], bl[j], cf[i][j]);
                    wmma::mma_sync(cf[i][j], al[i], bh[j], cf[i][j]);
                }
        }
    }

    __syncthreads();
    float* sC = (float*)smemh;
    #pragma unroll
    for (int i = 0; i < 4; i++)
        #pragma unroll
        for (int j = 0; j < 4; j++)
            wmma::store_matrix_sync(&sC[(wm + i*16)*132 + wn + j*16], cf[i][j], 132,
                                    wmma::mem_row_major);
    __syncthreads();

    #pragma unroll
    for (int i = 0; i < 32; i++) {
        int idx = tid + i * 128;
        int r = idx >> 5, cv = idx & 31;
        float4 v = *(const float4*)&sC[r*132 + cv*4];
        int grow = bm + r, gc = bn + cv*4;
        if (bias) {
            v.x += bias[gc+0]; v.y += bias[gc+1]; v.z += bias[gc+2]; v.w += bias[gc+3];
        }
        if (RANK1) {
            float rs = rowscale[grow];
            v.x += rs * coladd[gc+0]; v.y += rs * coladd[gc+1];
            v.z += rs * coladd[gc+2]; v.w += rs * coladd[gc+3];
        }
        if (RELU) {
            v.x = fmaxf(v.x, 0.f); v.y = fmaxf(v.y, 0.f);
            v.z = fmaxf(v.z, 0.f); v.w = fmaxf(v.w, 0.f);
        }
        long off = (long)grow * N + gc;
        if (SPLIT_OUT) {
            float vv[4] = {v.x, v.y, v.z, v.w};
            __nv_bfloat16 hh[4], ll[4];
            #pragma unroll
            for (int q = 0; q < 4; q++) {
                hh[q] = __float2bfloat16(vv[q]);
                ll[q] = __float2bfloat16(vv[q] - __bfloat162float(hh[q]));
            }
            *(__nv_bfloat162*)(Chi + off)     = __halves2bfloat162(hh[0], hh[1]);
            *(__nv_bfloat162*)(Chi + off + 2) = __halves2bfloat162(hh[2], hh[3]);
            *(__nv_bfloat162*)(Clo + off)     = __halves2bfloat162(ll[0], ll[1]);
            *(__nv_bfloat162*)(Clo + off + 2) = __halves2bfloat162(ll[2], ll[3]);
        } else {
            *(float4*)&Cf[off] = v;
        }
    }
}

// ============================================================
// gemm_v2 (tf32): medium GEMMs (qkv, mixed, token_updates)
// ============================================================
#define V2_A (128*36)
#define V2_B (32*132)
#define V2_STG (V2_A + V2_B)
#define V2_SMEM (3*V2_STG*4)

template<bool RELU>
__global__ void __launch_bounds__(128, 2)
gemm_v2(const float* __restrict__ Ag, const float* __restrict__ Bg,
        const float* __restrict__ bias, const float* __restrict__ rowscale,
        const float* __restrict__ coladd, float* __restrict__ Cg,
        int M, int N, int K, int lda, int ldb, int ldc,
        long strideA, long strideB, long strideC)
{
    extern __shared__ float smemf[];
    const float* A = Ag + blockIdx.z * strideA;
    const float* B = Bg + blockIdx.z * strideB;
    float*       C = Cg + blockIdx.z * strideC;

    const int bm = blockIdx.y * 128;
    const int bn = blockIdx.x * 128;
    const int tid = threadIdx.x;
    const int warp = tid >> 5;
    const int wm = (warp >> 1) * 64;
    const int wn = (warp & 1) * 64;

    wmma::fragment<wmma::accumulator, 16,16,8, float> cf[4][4];
    #pragma unroll
    for (int i = 0; i < 4; i++)
        #pragma unroll
        for (int j = 0; j < 4; j++) wmma::fill_fragment(cf[i][j], 0.0f);

    const int ar = tid >> 3, ac = tid & 7;
    const int br = tid >> 5, bc = tid & 31;

    auto issue = [&](int k0, int st) {
        float* sA = smemf + st * V2_STG;
        float* sB = sA + V2_A;
        #pragma unroll
        for (int i = 0; i < 8; i++) {
            int m = ar + i * 16;
            cp16(&sA[m*36 + ac*4], &A[(long)(bm + m) * lda + k0 + ac*4]);
        }
        #pragma unroll
        for (int i = 0; i < 8; i++) {
            int k = br + i * 4;
            cp16(&sB[k*132 + bc*4], &B[(long)(k0 + k) * ldb + bn + bc*4]);
        }
    };

    const int nIter = K >> 5;
    issue(0, 0); cp_commit();
    if (nIter > 1) { issue(32, 1); cp_commit(); }

    for (int it = 0; it < nIter; it++) {
        if (it + 1 < nIter) cp_wait<1>(); else cp_wait<0>();
        __syncthreads();

        int jn = it + 2;
        if (jn < nIter) { issue(jn << 5, jn % 3); cp_commit(); }

        const float* cA = smemf + (it % 3) * V2_STG;
        const float* cB = cA + V2_A;
        #pragma unroll
        for (int ks = 0; ks < 4; ks++) {
            wmma::fragment<wmma::matrix_a,16,16,8,wmma::precision::tf32,wmma::row_major> af[4];
            wmma::fragment<wmma::matrix_b,16,16,8,wmma::precision::tf32,wmma::row_major> bf[4];
            #pragma unroll
            for (int i = 0; i < 4; i++)
                wmma::load_matrix_sync(af[i], &cA[(wm + i*16)*36 + ks*8], 36);
            #pragma unroll
            for (int j = 0; j < 4; j++)
                wmma::load_matrix_sync(bf[j], &cB[(ks*8)*132 + wn + j*16], 132);
            #pragma unroll
            for (int i = 0; i < 4; i++)
                #pragma unroll
                for (int j = 0; j < 4; j++)
                    wmma::mma_sync(cf[i][j], af[i], bf[j], cf[i][j]);
        }
    }

    __syncthreads();
    float* sC = smemf;
    #pragma unroll
    for (int i = 0; i < 4; i++)
        #pragma unroll
        for (int j = 0; j < 4; j++)
            wmma::store_matrix_sync(&sC[(wm + i*16)*132 + wn + j*16], cf[i][j], 132,
                                    wmma::mem_row_major);
    __syncthreads();

    #pragma unroll
    for (int i = 0; i < 32; i++) {
        int idx = tid + i * 128;
        int r = idx >> 5, cv = idx & 31;
        float4 v = *(const float4*)&sC[r*132 + cv*4];
        int grow = bm + r, gc = bn + cv*4;
        if (bias) {
            v.x += bias[gc+0]; v.y += bias[gc+1]; v.z += bias[gc+2]; v.w += bias[gc+3];
        }
        if (rowscale) {
            float rs = rowscale[grow];
            v.x += rs * coladd[gc+0]; v.y += rs * coladd[gc+1];
            v.z += rs * coladd[gc+2]; v.w += rs * coladd[gc+3];
        }
        if (RELU) {
            v.x = fmaxf(v.x, 0.f); v.y = fmaxf(v.y, 0.f);
            v.z = fmaxf(v.z, 0.f); v.w = fmaxf(v.w, 0.f);
        }
        v.x = rtf(v.x); v.y = rtf(v.y); v.z = rtf(v.z); v.w = rtf(v.w);
        *(float4*)&C[(long)grow * ldc + gc] = v;
    }
}

// ============================================================
// gemm64: anchors (TRANS_A). Pre-rounded inputs.
// ============================================================
template<bool TRANS_A, bool RELU>
__global__ void gemm64(const float* __restrict__ Ag, const float* __restrict__ Bg,
                       const float* __restrict__ bias, const float* __restrict__ rowscale,
                       const float* __restrict__ coladd, float* __restrict__ Cg,
                       int M, int N, int K, int lda, int ldb, int ldc,
                       long strideA, long strideB, long strideC)
{
    constexpr int BM = 64, BN = 64, BK = 32;
    __shared__ __align__(32) float sA[BM*36];
    __shared__ __align__(32) float sB[BK*68];
    __shared__ __align__(32) float sC[64*68];

    const float* A = Ag + blockIdx.z * strideA;
    const float* B = Bg + blockIdx.z * strideB;
    float*       C = Cg + blockIdx.z * strideC;

    const int bm = blockIdx.y * BM;
    const int bn = blockIdx.x * BN;
    const int tid  = threadIdx.x;
    const int warp = tid >> 5;
    const int wm = (warp >> 1) * 32;
    const int wn = (warp & 1) * 32;

    wmma::fragment<wmma::accumulator, 16,16,8, float> cf[2][2];
    #pragma unroll
    for (int i = 0; i < 2; i++)
        #pragma unroll
        for (int j = 0; j < 2; j++) wmma::fill_fragment(cf[i][j], 0.0f);

    for (int k0 = 0; k0 < K; k0 += BK) {
        #pragma unroll
        for (int it = 0; it < 16; it++) {
            int idx = tid + it * 128;
            if (!TRANS_A) {
                int m = idx >> 5, k = idx & 31;
                sA[m*36 + k] = A[(long)(bm + m) * lda + (k0 + k)];
            } else {
                int m = idx & 63, k = idx >> 6;
                sA[m*36 + k] = A[(long)(k0 + k) * lda + (bm + m)];
            }
        }
        #pragma unroll
        for (int it = 0; it < 16; it++) {
            int idx = tid + it * 128;
            int n = idx & 63, k = idx >> 6;
            sB[k*68 + n] = B[(long)(k0 + k) * ldb + (bn + n)];
        }
        __syncthreads();

        #pragma unroll
        for (int ks = 0; ks < 4; ks++) {
            wmma::fragment<wmma::matrix_a,16,16,8,wmma::precision::tf32,wmma::row_major> af[2];
            wmma::fragment<wmma::matrix_b,16,16,8,wmma::precision::tf32,wmma::row_major> bf[2];
            #pragma unroll
            for (int i = 0; i < 2; i++)
                wmma::load_matrix_sync(af[i], &sA[(wm + i*16)*36 + ks*8], 36);
            #pragma unroll
            for (int j = 0; j < 2; j++)
                wmma::load_matrix_sync(bf[j], &sB[(ks*8)*68 + wn + j*16], 68);
            #pragma unroll
            for (int i = 0; i < 2; i++)
                #pragma unroll
                for (int j = 0; j < 2; j++)
                    wmma::mma_sync(cf[i][j], af[i], bf[j], cf[i][j]);
        }
        __syncthreads();
    }

    #pragma unroll
    for (int i = 0; i < 2; i++)
        #pragma unroll
        for (int j = 0; j < 2; j++)
            wmma::store_matrix_sync(&sC[(wm + i*16)*68 + wn + j*16], cf[i][j], 68,
                                    wmma::mem_row_major);
    __syncthreads();

    #pragma unroll
    for (int it = 0; it < 32; it++) {
        int idx = tid + it * 128;
        int r = idx >> 6, c = idx & 63;
        float v = sC[r*68 + c];
        int grow = bm + r, gcol = bn + c;
        if (bias)     v += bias[gcol];
        if (rowscale) v += rowscale[grow] * coladd[gcol];
        if (RELU)     v = fmaxf(v, 0.0f);
        C[(long)grow * ldc + gcol] = rtf(v);
    }
}

// ---- fold energy path ----
__global__ void prep_uv(const float* __restrict__ rm_w1, const float* __restrict__ rm_b1,
                        const float* __restrict__ ep_w, const float* __restrict__ ep_b)
{
    int j = blockIdx.x * blockDim.x + threadIdx.x;
    if (j >= ND) return;
    float u = 0.f, v = 0.f;
    #pragma unroll 8
    for (int a = 0; a < NA; a++) {
        float w = rm_w1[(long)(ND + a) * ND + j];
        u += ep_w[a] * w;
        v += ep_b[a] * w;
    }
    g_uvec[j] = u;
    g_bvec[j] = v + rm_b1[j];
}

// ---- softmax over A=64; reads padded logits (ld=128), tf32-rounded rw ----
__global__ void softmax64()
{
    int row  = blockIdx.x * 8 + (threadIdx.x >> 5);
    int lane = threadIdx.x & 31;
    const float* lr = g_logits + (long)row * 128;
    float v0 = lr[lane], v1 = lr[lane + 32];
    float m = fmaxf(v0, v1);
    #pragma unroll
    for (int o = 16; o > 0; o >>= 1) m = fmaxf(m, __shfl_xor_sync(0xffffffffu, m, o));
    v0 = expf(v0 - m); v1 = expf(v1 - m);
    float s = v0 + v1;
    #pragma unroll
    for (int o = 16; o > 0; o >>= 1) s += __shfl_xor_sync(0xffffffffu, s, o);
    float inv = 1.0f / s;
    float* rw = g_rw + (long)row * 64;
    rw[lane] = rtf(v0 * inv); rw[lane + 32] = rtf(v1 * inv);
}

// ---- anchor self-attention; outputs tf32-rounded ctx ----
__global__ void attn_kernel()
{
    int h = blockIdx.x, b = blockIdx.y;
    const float* base = g_qkv + (long)b * NA * 3 * ND;
    __shared__ float sc[64*64];
    int tid = threadIdx.x;
    const float scale = 0.08838834764831845f;

    #pragma unroll
    for (int it = 0; it < 16; it++) {
        int idx = tid + it * 256;
        int i = idx >> 6, j = idx & 63;
        const float* q = base + (long)i * 3 * ND + h * NHD;
        const float* k = base + (long)j * 3 * ND + ND + h * NHD;
        float acc = 0.f;
        #pragma unroll 8
        for (int d = 0; d < NHD; d++) acc += q[d] * k[d];
        sc[i*64 + j] = acc * scale;
    }
    __syncthreads();

    int warp = tid >> 5, lane = tid & 31;
    for (int r = warp; r < 64; r += 8) {
        float v0 = sc[r*64 + lane], v1 = sc[r*64 + lane + 32];
        float m = fmaxf(v0, v1);
        #pragma unroll
        for (int o = 16; o > 0; o >>= 1) m = fmaxf(m, __shfl_xor_sync(0xffffffffu, m, o));
        v0 = expf(v0 - m); v1 = expf(v1 - m);
        float s = v0 + v1;
        #pragma unroll
        for (int o = 16; o > 0; o >>= 1) s += __shfl_xor_sync(0xffffffffu, s, o);
        float inv = 1.0f / s;
        sc[r*64 + lane] = v0 * inv; sc[r*64 + lane + 32] = v1 * inv;
    }
    __syncthreads();

    #pragma unroll
    for (int it = 0; it < 32; it++) {
        int idx = tid + it * 256;
        int i = idx >> 7, d = idx & 127;
        const float* v = base + 2 * ND + h * NHD + d;
        float acc = 0.f;
        #pragma unroll 8
        for (int j = 0; j < 64; j++) acc += sc[i*64 + j] * v[(long)j * 3 * ND];
        g_ctx[((long)b * NA + i) * ND + h * NHD + d] = rtf(acc);
    }
}

__device__ __forceinline__ float blockReduceSum(float v)
{
    __shared__ float sh[9];
    __syncthreads();
    int lane = threadIdx.x & 31, warp = threadIdx.x >> 5;
    #pragma unroll
    for (int o = 16; o > 0; o >>= 1) v += __shfl_xor_sync(0xffffffffu, v, o);
    if (lane == 0) sh[warp] = v;
    __syncthreads();
    if (warp == 0) {
        float t = (lane < 8) ? sh[lane] : 0.f;
        #pragma unroll
        for (int o = 4; o > 0; o >>= 1) t += __shfl_xor_sync(0xffffffffu, t, o);
        if (lane == 0) sh[8] = t;
    }
    __syncthreads();
    return sh[8];
}

// ---- out = LayerNorm(X + Y) * g + b ; optional bf16 split side-output ----
__global__ void add_ln(const float* __restrict__ X, const float* __restrict__ Y,
                       const float* __restrict__ gam, const float* __restrict__ bet,
                       float* __restrict__ out,
                       __nv_bfloat16* __restrict__ ohi, __nv_bfloat16* __restrict__ olo)
{
    long row = blockIdx.x;
    int tid = threadIdx.x;
    float vals[4];
    float s = 0.f;
    #pragma unroll
    for (int i = 0; i < 4; i++) {
        int d = tid + i * 256;
        float v = X[row * ND + d] + Y[row * ND + d];
        vals[i] = v; s += v;
    }
    float mean = blockReduceSum(s) * (1.0f / ND);
    float vs = 0.f;
    #pragma unroll
    for (int i = 0; i < 4; i++) { float t = vals[i] - mean; vs += t * t; }
    float var = blockReduceSum(vs) * (1.0f / ND);
    float inv = rsqrtf(var + 1e-5f);
    #pragma unroll
    for (int i = 0; i < 4; i++) {
        int d = tid + i * 256;
        float o = (vals[i] - mean) * inv * gam[d] + bet[d];
        out[row * ND + d] = o;
        if (ohi) {
            __nv_bfloat16 h = __float2bfloat16(o);
            ohi[row * ND + d] = h;
            olo[row * ND + d] = __float2bfloat16(o - __bfloat162float(h));
        }
    }
}

// ============================================================
extern "C" void kernel_launch(void* const* d_in, const int* in_sizes, int n_in,
                              void* d_out, int out_size)
{
    const float* x     = (const float*)d_in[0];
    const float* efas  = (const float*)d_in[1];
    const float* ep_w  = (const float*)d_in[2];
    const float* ep_b  = (const float*)d_in[3];
    const float* rm_w1 = (const float*)d_in[5];
    const float* rm_b1 = (const float*)d_in[6];
    const float* rm_w2 = (const float*)d_in[7];
    const float* rm_b2 = (const float*)d_in[8];
    const float* in_w  = (const float*)d_in[9];
    const float* in_b  = (const float*)d_in[10];
    const float* ow    = (const float*)d_in[11];
    const float* ob    = (const float*)d_in[12];
    const float* fw1   = (const float*)d_in[13];
    const float* fb1   = (const float*)d_in[14];
    const float* fw2   = (const float*)d_in[15];
    const float* fb2   = (const float*)d_in[16];
    const float* l1g   = (const float*)d_in[17];
    const float* l1b   = (const float*)d_in[18];
    const float* l2g   = (const float*)d_in[19];
    const float* l2b   = (const float*)d_in[20];
    float* out = (float*)d_out;

    float *p_logits, *p_rw, *p_anchors, *p_qkv, *p_ctx, *p_mixed,
          *p_h, *p_f, *p_u, *p_bv, *p_b2p;
    float *p_xr, *p_inr, *p_owr;
    __nv_bfloat16 *p_xhi, *p_xlo, *p_w1hi, *p_w1lo, *p_hidhi, *p_hidlo,
                  *p_w2phi, *p_w2plo, *p_hhi, *p_hlo,
                  *p_f1hi, *p_f1lo, *p_f2hi, *p_f2lo, *p_thi, *p_tlo;
    cudaGetSymbolAddress((void**)&p_logits,  g_logits);
    cudaGetSymbolAddress((void**)&p_rw,      g_rw);
    cudaGetSymbolAddress((void**)&p_anchors, g_anchors);
    cudaGetSymbolAddress((void**)&p_qkv,     g_qkv);
    cudaGetSymbolAddress((void**)&p_ctx,     g_ctx);
    cudaGetSymbolAddress((void**)&p_mixed,   g_mixed);
    cudaGetSymbolAddress((void**)&p_h,       g_h);
    cudaGetSymbolAddress((void**)&p_f,       g_f);
    cudaGetSymbolAddress((void**)&p_u,       g_uvec);
    cudaGetSymbolAddress((void**)&p_bv,      g_bvec);
    cudaGetSymbolAddress((void**)&p_b2p,     g_b2p);
    cudaGetSymbolAddress((void**)&p_xr,      g_xr);
    cudaGetSymbolAddress((void**)&p_inr,     g_inr);
    cudaGetSymbolAddress((void**)&p_owr,     g_owr);
    cudaGetSymbolAddress((void**)&p_xhi,     g_xhi);
    cudaGetSymbolAddress((void**)&p_xlo,     g_xlo);
    cudaGetSymbolAddress((void**)&p_w1hi,    g_w1hi);
    cudaGetSymbolAddress((void**)&p_w1lo,    g_w1lo);
    cudaGetSymbolAddress((void**)&p_hidhi,   g_hidhi);
    cudaGetSymbolAddress((void**)&p_hidlo,   g_hidlo);
    cudaGetSymbolAddress((void**)&p_w2phi,   g_w2phi);
    cudaGetSymbolAddress((void**)&p_w2plo,   g_w2plo);
    cudaGetSymbolAddress((void**)&p_hhi,     g_hhi);
    cudaGetSymbolAddress((void**)&p_hlo,     g_hlo);
    cudaGetSymbolAddress((void**)&p_f1hi,    g_f1hi);
    cudaGetSymbolAddress((void**)&p_f1lo,    g_f1lo);
    cudaGetSymbolAddress((void**)&p_f2hi,    g_f2hi);
    cudaGetSymbolAddress((void**)&p_f2lo,    g_f2lo);
    cudaGetSymbolAddress((void**)&p_thi,     g_thi);
    cudaGetSymbolAddress((void**)&p_tlo,     g_tlo);

    static bool attr_set = false;
    if (!attr_set) {
        cudaFuncSetAttribute(gemm_v2<false>, cudaFuncAttributeMaxDynamicSharedMemorySize, V2_SMEM);
        cudaFuncSetAttribute(gemm_bf16s<true,true,true>,   cudaFuncAttributeMaxDynamicSharedMemorySize, BF_SMEM);
        cudaFuncSetAttribute(gemm_bf16s<true,true,false>,  cudaFuncAttributeMaxDynamicSharedMemorySize, BF_SMEM);
        cudaFuncSetAttribute(gemm_bf16s<false,false,false>,cudaFuncAttributeMaxDynamicSharedMemorySize, BF_SMEM);
        attr_set = true;
    }

    dim3 blk64(128), blk128(128);
    auto rl = [](long n) { return (unsigned)((n/4 + 255) / 256); };
    auto sl = [](long n) { return (unsigned)((n + 255) / 256); };

    // Launch order: hidden GEMM at index 3 (ncu profiles idx 3).
    prep_uv<<<4, 256>>>(rm_w1, rm_b1, ep_w, ep_b);                                  // 0
    split_bf<<<sl((long)NBS*ND), 256>>>(x, p_xhi, p_xlo, (long)NBS*ND);             // 1
    split_bf<<<sl((long)ND*ND), 256>>>(rm_w1, p_w1hi, p_w1lo, (long)ND*ND);         // 2

    // 3) hidden = relu(x@W1x + efas*u + bvec)  bf16s, split out  ← ncu target
    gemm_bf16s<true,true,true><<<dim3(ND/128, NBS/128), blk128, BF_SMEM>>>(
        p_xhi, p_xlo, p_w1hi, p_w1lo, p_bv, efas, p_u,
        nullptr, p_hidhi, p_hidlo, NBS, ND, ND);

    roundtf<<<rl((long)NBS*ND), 256>>>((const float4*)x, (float4*)p_xr, (long)NBS*ND/4);
    pad_w2_bf<<<512, 256>>>(rm_w2, rm_b2);
    split_bf<<<sl((long)ND*4*ND), 256>>>(fw1, p_f1hi, p_f1lo, (long)ND*4*ND);
    split_bf<<<sl((long)4*ND*ND), 256>>>(fw2, p_f2hi, p_f2lo, (long)4*ND*ND);
    roundtf<<<rl((long)ND*3*ND), 256>>>((const float4*)in_w, (float4*)p_inr, (long)ND*3*ND/4);
    roundtf<<<rl((long)ND*ND), 256>>>((const float4*)ow,     (float4*)p_owr, (long)ND*ND/4);

    // logits(padded N=128) = hidden @ w2p + b2p   bf16s
    gemm_bf16s<false,false,false><<<dim3(1, NBS/128), blk128, BF_SMEM>>>(
        p_hidhi, p_hidlo, p_w2phi, p_w2plo, p_b2p, nullptr, nullptr,
        p_logits, nullptr, nullptr, NBS, 128, ND);

    softmax64<<<NBS/8, 256>>>();

    // anchors[b] = rw[b]^T @ xr[b]                batched tf32
    gemm64<true, false><<<dim3(ND/64, 1, NB), blk64>>>(
        p_rw, p_xr, nullptr, nullptr, nullptr, p_anchors, NA, ND, NS,
        NA, ND, ND, (long)NS*NA, (long)NS*ND, (long)NA*ND);

    // qkv = anchors @ inr + in_b                  tf32
    gemm_v2<false><<<dim3(3*ND/128, NB*NA/128), blk128, V2_SMEM>>>(
        p_anchors, p_inr, in_b, nullptr, nullptr, p_qkv, NB*NA, 3*ND, ND, ND, 3*ND, 3*ND, 0, 0, 0);

    attn_kernel<<<dim3(NH, NB), 256>>>();

    // mixed = ctx @ owr + ob                      tf32
    gemm_v2<false><<<dim3(ND/128, NB*NA/128), blk128, V2_SMEM>>>(
        p_ctx, p_owr, ob, nullptr, nullptr, p_mixed, NB*NA, ND, ND, ND, ND, ND, 0, 0, 0);

    // token_updates[b] = rw[b] @ mixed[b]         tf32, batched
    gemm_v2<false><<<dim3(ND/128, NS/128, NB), blk128, V2_SMEM>>>(
        p_rw, p_mixed, nullptr, nullptr, nullptr, p_f, NS, ND, NA,
        NA, ND, ND, (long)NS*NA, (long)NA*ND, (long)NS*ND);

    // h = LN1(x + token_updates)  (fp32 for LN2 + bf16 hi/lo for ffn1)
    add_ln<<<NBS, 256>>>(x, p_f, l1g, l1b, p_h, p_hhi, p_hlo);

    // t = relu(h @ fw1 + fb1)   bf16s, split out  [32768,1024]x[1024,4096]
    gemm_bf16s<true,true,false><<<dim3(4*ND/128, NBS/128), blk128, BF_SMEM>>>(
        p_hhi, p_hlo, p_f1hi, p_f1lo, fb1, nullptr, nullptr,
        nullptr, p_thi, p_tlo, NBS, 4*ND, ND);

    // f = t @ fw2 + fb2         bf16s            [32768,4096]x[4096,1024]
    gemm_bf16s<false,false,false><<<dim3(ND/128, NBS/128), blk128, BF_SMEM>>>(
        p_thi, p_tlo, p_f2hi, p_f2lo, fb2, nullptr, nullptr,
        p_f, nullptr, nullptr, NBS, ND, 4*ND);

    // out = LN2(h + f)  (full precision)
    add_ln<<<NBS, 256>>>(p_h, p_f, l2g, l2b, out, nullptr, nullptr);
}

// round 17
// speedup vs baseline: 1.2936x; 1.0121x over previous
#include <cuda_runtime.h>
#include <cuda_bf16.h>
#include <mma.h>
#include <cstdint>

using namespace nvcuda;

#define NB  8
#define NS  4096
#define ND  1024
#define NA  64
#define NH  8
#define NHD 128
#define NBS (NB*NS)

// ---- scratch (static device globals: alloc-free per harness rules) ----
__device__ float g_logits[NBS*128];         // padded logits, ld=128
__device__ float g_rw[NBS*NA];              // fp32 tf32-rounded (token_updates A)
__device__ float g_qkv[NB*NA*3*ND];
__device__ float g_mixed[NB*NA*ND];
__device__ float g_h[NBS*ND];
__device__ float g_f[NBS*ND];
__device__ float g_uvec[ND];
__device__ float g_bvec[ND];
__device__ float g_b2p[128];
// bf16 split operands
__device__ __nv_bfloat16 g_xhi[NBS*ND],  g_xlo[NBS*ND];
__device__ __nv_bfloat16 g_w1hi[ND*ND],  g_w1lo[ND*ND];
__device__ __nv_bfloat16 g_hidhi[NBS*ND], g_hidlo[NBS*ND];
__device__ __nv_bfloat16 g_w2phi[ND*128], g_w2plo[ND*128];
__device__ __nv_bfloat16 g_rwThi[NB*NA*NS], g_rwTlo[NB*NA*NS];   // [b][a][s]
__device__ __nv_bfloat16 g_anchhi[NB*NA*ND], g_anchlo[NB*NA*ND];
__device__ __nv_bfloat16 g_inhi[ND*3*ND], g_inlo[ND*3*ND];
__device__ __nv_bfloat16 g_ctxhi[NB*NA*ND], g_ctxlo[NB*NA*ND];
__device__ __nv_bfloat16 g_owhi[ND*ND],  g_owlo[ND*ND];
__device__ __nv_bfloat16 g_hhi[NBS*ND],  g_hlo[NBS*ND];
__device__ __nv_bfloat16 g_f1hi[(long)ND*4*ND], g_f1lo[(long)ND*4*ND];
__device__ __nv_bfloat16 g_f2hi[(long)4*ND*ND], g_f2lo[(long)4*ND*ND];
__device__ __nv_bfloat16 g_thi[(long)NBS*4*ND], g_tlo[(long)NBS*4*ND];

// ---- cp.async helpers ----
__device__ __forceinline__ void cp16(void* smem_dst, const void* gsrc) {
    uint32_t s = (uint32_t)__cvta_generic_to_shared(smem_dst);
    asm volatile("cp.async.cg.shared.global [%0], [%1], 16;\n" :: "r"(s), "l"(gsrc));
}
__device__ __forceinline__ void cp_commit() {
    asm volatile("cp.async.commit_group;\n");
}
template<int N> __device__ __forceinline__ void cp_wait() {
    asm volatile("cp.async.wait_group %0;\n" :: "n"(N));
}

__device__ __forceinline__ float rtf(float v) { return wmma::__float_to_tf32(v); }

// ---- fp32 -> bf16 (hi, lo) split ----
__global__ void split_bf(const float* __restrict__ src,
                         __nv_bfloat16* __restrict__ hi, __nv_bfloat16* __restrict__ lo,
                         long n)
{
    long i = (long)blockIdx.x * blockDim.x + threadIdx.x;
    if (i >= n) return;
    float v = src[i];
    __nv_bfloat16 h = __float2bfloat16(v);
    hi[i] = h;
    lo[i] = __float2bfloat16(v - __bfloat162float(h));
}

// ---- pad rm_w2 [1024,64] -> [1024,128] bf16 hi/lo; pad rm_b2 fp32 ----
__global__ void pad_w2_bf(const float* __restrict__ w2, const float* __restrict__ b2)
{
    int i = blockIdx.x * blockDim.x + threadIdx.x;      // 0..131071
    int j = i >> 7, c = i & 127;
    float v = (c < NA) ? w2[j * NA + c] : 0.0f;
    __nv_bfloat16 h = __float2bfloat16(v);
    g_w2phi[i] = h;
    g_w2plo[i] = __float2bfloat16(v - __bfloat162float(h));
    if (i < 128) g_b2p[i] = (i < NA) ? b2[i] : 0.0f;
}

// ---- fold energy path ----
__global__ void prep_uv(const float* __restrict__ rm_w1, const float* __restrict__ rm_b1,
                        const float* __restrict__ ep_w, const float* __restrict__ ep_b)
{
    int j = blockIdx.x * blockDim.x + threadIdx.x;
    if (j >= ND) return;
    float u = 0.f, v = 0.f;
    #pragma unroll 8
    for (int a = 0; a < NA; a++) {
        float w = rm_w1[(long)(ND + a) * ND + j];
        u += ep_w[a] * w;
        v += ep_b[a] * w;
    }
    g_uvec[j] = u;
    g_bvec[j] = v + rm_b1[j];
}

// ============================================================
// gemm_bf16s: C[M,N] = (Ahi+Alo)@(Bhi+Blo) + bias (+rank1)(relu)
// bf16 2-way split, 3 MMAs per k16 step, fp32 accum.
// CTA 128x128, 128 threads = 4 warps (2x2), each 64x64.
// BK=32, 3-stage cp.async, ~111KB smem -> 2 CTAs/SM.
// SPLIT_OUT: write bf16 hi/lo; else fp32 (tf32-rounded).
// ============================================================
#define BF_AH (128*40)
#define BF_BH (32*136)
#define BF_STG (2*BF_AH + 2*BF_BH)
#define BF_SMEM (3*BF_STG*2)

template<bool RELU, bool SPLIT_OUT, bool RANK1>
__global__ void __launch_bounds__(128, 2)
gemm_bf16s(const __nv_bfloat16* __restrict__ Ahi, const __nv_bfloat16* __restrict__ Alo,
           const __nv_bfloat16* __restrict__ Bhi, const __nv_bfloat16* __restrict__ Blo,
           const float* __restrict__ bias, const float* __restrict__ rowscale,
           const float* __restrict__ coladd,
           float* __restrict__ Cf, __nv_bfloat16* __restrict__ Chi,
           __nv_bfloat16* __restrict__ Clo,
           int M, int N, int K)
{
    extern __shared__ __nv_bfloat16 smemh[];
    const int bm = blockIdx.y * 128;
    const int bn = blockIdx.x * 128;
    const int tid = threadIdx.x;
    const int warp = tid >> 5;
    const int wm = (warp >> 1) * 64;
    const int wn = (warp & 1) * 64;

    wmma::fragment<wmma::accumulator, 16,16,16, float> cf[4][4];
    #pragma unroll
    for (int i = 0; i < 4; i++)
        #pragma unroll
        for (int j = 0; j < 4; j++) wmma::fill_fragment(cf[i][j], 0.0f);

    const int am = tid >> 2, ak = tid & 3;
    const int bk = tid >> 4, bn8 = tid & 15;

    auto issue = [&](int k0, int st) {
        __nv_bfloat16* sAh = smemh + st * BF_STG;
        __nv_bfloat16* sAl = sAh + BF_AH;
        __nv_bfloat16* sBh = sAl + BF_AH;
        __nv_bfloat16* sBl = sBh + BF_BH;
        #pragma unroll
        for (int i = 0; i < 4; i++) {
            int m = am + i * 32;
            long go = (long)(bm + m) * K + k0 + ak * 8;
            cp16(&sAh[m*40 + ak*8], Ahi + go);
            cp16(&sAl[m*40 + ak*8], Alo + go);
        }
        #pragma unroll
        for (int i = 0; i < 4; i++) {
            int k = bk + i * 8;
            long go = (long)(k0 + k) * N + bn + bn8 * 8;
            cp16(&sBh[k*136 + bn8*8], Bhi + go);
            cp16(&sBl[k*136 + bn8*8], Blo + go);
        }
    };

    const int nIter = K >> 5;
    issue(0, 0); cp_commit();
    if (nIter > 1) { issue(32, 1); cp_commit(); }

    for (int it = 0; it < nIter; it++) {
        if (it + 1 < nIter) cp_wait<1>(); else cp_wait<0>();
        __syncthreads();

        int jn = it + 2;
        if (jn < nIter) { issue(jn << 5, jn % 3); cp_commit(); }

        const __nv_bfloat16* cAh = smemh + (it % 3) * BF_STG;
        const __nv_bfloat16* cAl = cAh + BF_AH;
        const __nv_bfloat16* cBh = cAl + BF_AH;
        const __nv_bfloat16* cBl = cBh + BF_BH;

        #pragma unroll
        for (int ks = 0; ks < 2; ks++) {
            wmma::fragment<wmma::matrix_a,16,16,16,__nv_bfloat16,wmma::row_major> ah[4], al[4];
            wmma::fragment<wmma::matrix_b,16,16,16,__nv_bfloat16,wmma::row_major> bh[4], bl[4];
            #pragma unroll
            for (int i = 0; i < 4; i++) {
                wmma::load_matrix_sync(ah[i], &cAh[(wm + i*16)*40 + ks*16], 40);
                wmma::load_matrix_sync(al[i], &cAl[(wm + i*16)*40 + ks*16], 40);
            }
            #pragma unroll
            for (int j = 0; j < 4; j++) {
                wmma::load_matrix_sync(bh[j], &cBh[(ks*16)*136 + wn + j*16], 136);
                wmma::load_matrix_sync(bl[j], &cBl[(ks*16)*136 + wn + j*16], 136);
            }
            #pragma unroll
            for (int i = 0; i < 4; i++)
                #pragma unroll
                for (int j = 0; j < 4; j++) {
                    wmma::mma_sync(cf[i][j], ah[i], bh[j], cf[i][j]);
                    wmma::mma_sync(cf[i][j], ah[i], bl[j], cf[i][j]);
                    wmma::mma_sync(cf[i][j], al[i], bh[j], cf[i][j]);
                }
        }
    }

    __syncthreads();
    float* sC = (float*)smemh;
    #pragma unroll
    for (int i = 0; i < 4; i++)
        #pragma unroll
        for (int j = 0; j < 4; j++)
            wmma::store_matrix_sync(&sC[(wm + i*16)*132 + wn + j*16], cf[i][j], 132,
                                    wmma::mem_row_major);
    __syncthreads();

    #pragma unroll
    for (int i = 0; i < 32; i++) {
        int idx = tid + i * 128;
        int r = idx >> 5, cv = idx & 31;
        float4 v = *(const float4*)&sC[r*132 + cv*4];
        int grow = bm + r, gc = bn + cv*4;
        if (bias) {
            v.x += bias[gc+0]; v.y += bias[gc+1]; v.z += bias[gc+2]; v.w += bias[gc+3];
        }
        if (RANK1) {
            float rs = rowscale[grow];
            v.x += rs * coladd[gc+0]; v.y += rs * coladd[gc+1];
            v.z += rs * coladd[gc+2]; v.w += rs * coladd[gc+3];
        }
        if (RELU) {
            v.x = fmaxf(v.x, 0.f); v.y = fmaxf(v.y, 0.f);
            v.z = fmaxf(v.z, 0.f); v.w = fmaxf(v.w, 0.f);
        }
        long off = (long)grow * N + gc;
        if (SPLIT_OUT) {
            float vv[4] = {v.x, v.y, v.z, v.w};
            __nv_bfloat16 hh[4], ll[4];
            #pragma unroll
            for (int q = 0; q < 4; q++) {
                hh[q] = __float2bfloat16(vv[q]);
                ll[q] = __float2bfloat16(vv[q] - __bfloat162float(hh[q]));
            }
            *(__nv_bfloat162*)(Chi + off)     = __halves2bfloat162(hh[0], hh[1]);
            *(__nv_bfloat162*)(Chi + off + 2) = __halves2bfloat162(hh[2], hh[3]);
            *(__nv_bfloat162*)(Clo + off)     = __halves2bfloat162(ll[0], ll[1]);
            *(__nv_bfloat162*)(Clo + off + 2) = __halves2bfloat162(ll[2], ll[3]);
        } else {
            v.x = rtf(v.x); v.y = rtf(v.y); v.z = rtf(v.z); v.w = rtf(v.w);
            *(float4*)&Cf[off] = v;
        }
    }
}

// ============================================================
// gemm_bf16s64: BM=64 batched variant (anchors).
// C[b][64,N] = A[b][64,K] @ B[b][K,N]. 4 warps (2x2), each 32x64.
// ============================================================
#define B64_AH (64*40)
#define B64_BH (32*136)
#define B64_STG (2*B64_AH + 2*B64_BH)      // halves per stage = 13824
#define B64_SMEM (3*B64_STG*2)             // 82944 bytes

template<bool SPLIT_OUT>
__global__ void __launch_bounds__(128, 1)
gemm_bf16s64(const __nv_bfloat16* __restrict__ Ahi, const __nv_bfloat16* __restrict__ Alo,
             const __nv_bfloat16* __restrict__ Bhi, const __nv_bfloat16* __restrict__ Blo,
             float* __restrict__ Cf, __nv_bfloat16* __restrict__ Chi,
             __nv_bfloat16* __restrict__ Clo,
             int N, int K, long strideA, long strideB, long strideC)
{
    extern __shared__ __nv_bfloat16 smemh[];
    const __nv_bfloat16* Ah = Ahi + blockIdx.z * strideA;
    const __nv_bfloat16* Al = Alo + blockIdx.z * strideA;
    const __nv_bfloat16* Bh = Bhi + blockIdx.z * strideB;
    const __nv_bfloat16* Bl = Blo + blockIdx.z * strideB;

    const int bn = blockIdx.x * 128;
    const int tid = threadIdx.x;
    const int warp = tid >> 5;
    const int wm = (warp >> 1) * 32;   // 0,32
    const int wn = (warp & 1) * 64;    // 0,64

    wmma::fragment<wmma::accumulator, 16,16,16, float> cf[2][4];
    #pragma unroll
    for (int i = 0; i < 2; i++)
        #pragma unroll
        for (int j = 0; j < 4; j++) wmma::fill_fragment(cf[i][j], 0.0f);

    const int bk = tid >> 4, bn8 = tid & 15;

    auto issue = [&](int k0, int st) {
        __nv_bfloat16* sAh = smemh + st * B64_STG;
        __nv_bfloat16* sAl = sAh + B64_AH;
        __nv_bfloat16* sBh = sAl + B64_AH;
        __nv_bfloat16* sBl = sBh + B64_BH;
        #pragma unroll
        for (int i = 0; i < 2; i++) {
            int idx = tid + i * 128;           // 0..255
            int m = idx >> 2, c = idx & 3;
            long go = (long)m * K + k0 + c * 8;
            cp16(&sAh[m*40 + c*8], Ah + go);
            cp16(&sAl[m*40 + c*8], Al + go);
        }
        #pragma unroll
        for (int i = 0; i < 4; i++) {
            int k = bk + i * 8;
            long go = (long)(k0 + k) * N + bn + bn8 * 8;
            cp16(&sBh[k*136 + bn8*8], Bh + go);
            cp16(&sBl[k*136 + bn8*8], Bl + go);
        }
    };

    const int nIter = K >> 5;
    issue(0, 0); cp_commit();
    if (nIter > 1) { issue(32, 1); cp_commit(); }

    for (int it = 0; it < nIter; it++) {
        if (it + 1 < nIter) cp_wait<1>(); else cp_wait<0>();
        __syncthreads();

        int jn = it + 2;
        if (jn < nIter) { issue(jn << 5, jn % 3); cp_commit(); }

        const __nv_bfloat16* cAh = smemh + (it % 3) * B64_STG;
        const __nv_bfloat16* cAl = cAh + B64_AH;
        const __nv_bfloat16* cBh = cAl + B64_AH;
        const __nv_bfloat16* cBl = cBh + B64_BH;

        #pragma unroll
        for (int ks = 0; ks < 2; ks++) {
            wmma::fragment<wmma::matrix_a,16,16,16,__nv_bfloat16,wmma::row_major> ah[2], al[2];
            wmma::fragment<wmma::matrix_b,16,16,16,__nv_bfloat16,wmma::row_major> bh[4], bl[4];
            #pragma unroll
            for (int i = 0; i < 2; i++) {
                wmma::load_matrix_sync(ah[i], &cAh[(wm + i*16)*40 + ks*16], 40);
                wmma::load_matrix_sync(al[i], &cAl[(wm + i*16)*40 + ks*16], 40);
            }
            #pragma unroll
            for (int j = 0; j < 4; j++) {
                wmma::load_matrix_sync(bh[j], &cBh[(ks*16)*136 + wn + j*16], 136);
                wmma::load_matrix_sync(bl[j], &cBl[(ks*16)*136 + wn + j*16], 136);
            }
            #pragma unroll
            for (int i = 0; i < 2; i++)
                #pragma unroll
                for (int j = 0; j < 4; j++) {
                    wmma::mma_sync(cf[i][j], ah[i], bh[j], cf[i][j]);
                    wmma::mma_sync(cf[i][j], ah[i], bl[j], cf[i][j]);
                    wmma::mma_sync(cf[i][j], al[i], bh[j], cf[i][j]);
                }
        }
    }

    __syncthreads();
    float* sC = (float*)smemh;                 // 64*132 floats = 33.8KB
    #pragma unroll
    for (int i = 0; i < 2; i++)
        #pragma unroll
        for (int j = 0; j < 4; j++)
            wmma::store_matrix_sync(&sC[(wm + i*16)*132 + wn + j*16], cf[i][j], 132,
                                    wmma::mem_row_major);
    __syncthreads();

    #pragma unroll
    for (int i = 0; i < 16; i++) {
        int idx = tid + i * 128;               // 2048 float4 over 64x128
        int r = idx >> 5, cv = idx & 31;
        float4 v = *(const float4*)&sC[r*132 + cv*4];
        long off = blockIdx.z * strideC + (long)r * N + bn + cv*4;
        if (SPLIT_OUT) {
            float vv[4] = {v.x, v.y, v.z, v.w};
            __nv_bfloat16 hh[4], ll[4];
            #pragma unroll
            for (int q = 0; q < 4; q++) {
                hh[q] = __float2bfloat16(vv[q]);
                ll[q] = __float2bfloat16(vv[q] - __bfloat162float(hh[q]));
            }
            *(__nv_bfloat162*)(Chi + off)     = __halves2bfloat162(hh[0], hh[1]);
            *(__nv_bfloat162*)(Chi + off + 2) = __halves2bfloat162(hh[2], hh[3]);
            *(__nv_bfloat162*)(Clo + off)     = __halves2bfloat162(ll[0], ll[1]);
            *(__nv_bfloat162*)(Clo + off + 2) = __halves2bfloat162(ll[2], ll[3]);
        } else {
            *(float4*)&Cf[off] = v;
        }
    }
}

// ============================================================
// gemm_v2 (tf32): token_updates only (K=64, epilogue-bound)
// ============================================================
#define V2_A (128*36)
#define V2_B (32*132)
#define V2_STG (V2_A + V2_B)
#define V2_SMEM (3*V2_STG*4)

template<bool RELU>
__global__ void __launch_bounds__(128, 2)
gemm_v2(const float* __restrict__ Ag, const float* __restrict__ Bg,
        const float* __restrict__ bias, const float* __restrict__ rowscale,
        const float* __restrict__ coladd, float* __restrict__ Cg,
        int M, int N, int K, int lda, int ldb, int ldc,
        long strideA, long strideB, long strideC)
{
    extern __shared__ float smemf[];
    const float* A = Ag + blockIdx.z * strideA;
    const float* B = Bg + blockIdx.z * strideB;
    float*       C = Cg + blockIdx.z * strideC;

    const int bm = blockIdx.y * 128;
    const int bn = blockIdx.x * 128;
    const int tid = threadIdx.x;
    const int warp = tid >> 5;
    const int wm = (warp >> 1) * 64;
    const int wn = (warp & 1) * 64;

    wmma::fragment<wmma::accumulator, 16,16,8, float> cf[4][4];
    #pragma unroll
    for (int i = 0; i < 4; i++)
        #pragma unroll
        for (int j = 0; j < 4; j++) wmma::fill_fragment(cf[i][j], 0.0f);

    const int ar = tid >> 3, ac = tid & 7;
    const int br = tid >> 5, bc = tid & 31;

    auto issue = [&](int k0, int st) {
        float* sA = smemf + st * V2_STG;
        float* sB = sA + V2_A;
        #pragma unroll
        for (int i = 0; i < 8; i++) {
            int m = ar + i * 16;
            cp16(&sA[m*36 + ac*4], &A[(long)(bm + m) * lda + k0 + ac*4]);
        }
        #pragma unroll
        for (int i = 0; i < 8; i++) {
            int k = br + i * 4;
            cp16(&sB[k*132 + bc*4], &B[(long)(k0 + k) * ldb + bn + bc*4]);
        }
    };

    const int nIter = K >> 5;
    issue(0, 0); cp_commit();
    if (nIter > 1) { issue(32, 1); cp_commit(); }

    for (int it = 0; it < nIter; it++) {
        if (it + 1 < nIter) cp_wait<1>(); else cp_wait<0>();
        __syncthreads();

        int jn = it + 2;
        if (jn < nIter) { issue(jn << 5, jn % 3); cp_commit(); }

        const float* cA = smemf + (it % 3) * V2_STG;
        const float* cB = cA + V2_A;
        #pragma unroll
        for (int ks = 0; ks < 4; ks++) {
            wmma::fragment<wmma::matrix_a,16,16,8,wmma::precision::tf32,wmma::row_major> af[4];
            wmma::fragment<wmma::matrix_b,16,16,8,wmma::precision::tf32,wmma::row_major> bf[4];
            #pragma unroll
            for (int i = 0; i < 4; i++)
                wmma::load_matrix_sync(af[i], &cA[(wm + i*16)*36 + ks*8], 36);
            #pragma unroll
            for (int j = 0; j < 4; j++)
                wmma::load_matrix_sync(bf[j], &cB[(ks*8)*132 + wn + j*16], 132);
            #pragma unroll
            for (int i = 0; i < 4; i++)
                #pragma unroll
                for (int j = 0; j < 4; j++)
                    wmma::mma_sync(cf[i][j], af[i], bf[j], cf[i][j]);
        }
    }

    __syncthreads();
    float* sC = smemf;
    #pragma unroll
    for (int i = 0; i < 4; i++)
        #pragma unroll
        for (int j = 0; j < 4; j++)
            wmma::store_matrix_sync(&sC[(wm + i*16)*132 + wn + j*16], cf[i][j], 132,
                                    wmma::mem_row_major);
    __syncthreads();

    #pragma unroll
    for (int i = 0; i < 32; i++) {
        int idx = tid + i * 128;
        int r = idx >> 5, cv = idx & 31;
        float4 v = *(const float4*)&sC[r*132 + cv*4];
        int grow = bm + r, gc = bn + cv*4;
        if (bias) {
            v.x += bias[gc+0]; v.y += bias[gc+1]; v.z += bias[gc+2]; v.w += bias[gc+3];
        }
        if (rowscale) {
            float rs = rowscale[grow];
            v.x += rs * coladd[gc+0]; v.y += rs * coladd[gc+1];
            v.z += rs * coladd[gc+2]; v.w += rs * coladd[gc+3];
        }
        if (RELU) {
            v.x = fmaxf(v.x, 0.f); v.y = fmaxf(v.y, 0.f);
            v.z = fmaxf(v.z, 0.f); v.w = fmaxf(v.w, 0.f);
        }
        *(float4*)&C[(long)grow * ldc + gc] = v;
    }
}

// ---- softmax over A=64; emits fp32 rw (tf32-rounded) + transposed bf16 hi/lo ----
__global__ void softmax64()
{
    int row  = blockIdx.x * 8 + (threadIdx.x >> 5);
    int lane = threadIdx.x & 31;
    const float* lr = g_logits + (long)row * 128;
    float v0 = lr[lane], v1 = lr[lane + 32];
    float m = fmaxf(v0, v1);
    #pragma unroll
    for (int o = 16; o > 0; o >>= 1) m = fmaxf(m, __shfl_xor_sync(0xffffffffu, m, o));
    v0 = expf(v0 - m); v1 = expf(v1 - m);
    float s = v0 + v1;
    #pragma unroll
    for (int o = 16; o > 0; o >>= 1) s += __shfl_xor_sync(0xffffffffu, s, o);
    float inv = 1.0f / s;
    v0 *= inv; v1 *= inv;
    float* rw = g_rw + (long)row * 64;
    rw[lane] = rtf(v0); rw[lane + 32] = rtf(v1);

    // transposed bf16 split: rwT[b][a][s]
    int b = row >> 12, sidx = row & 4095;
    long t0 = ((long)b * NA + lane) * NS + sidx;
    long t1 = ((long)b * NA + lane + 32) * NS + sidx;
    __nv_bfloat16 h0 = __float2bfloat16(v0), h1 = __float2bfloat16(v1);
    g_rwThi[t0] = h0; g_rwTlo[t0] = __float2bfloat16(v0 - __bfloat162float(h0));
    g_rwThi[t1] = h1; g_rwTlo[t1] = __float2bfloat16(v1 - __bfloat162float(h1));
}

// ---- anchor self-attention; emits ctx bf16 hi/lo ----
__global__ void attn_kernel()
{
    int h = blockIdx.x, b = blockIdx.y;
    const float* base = g_qkv + (long)b * NA * 3 * ND;
    __shared__ float sc[64*64];
    int tid = threadIdx.x;
    const float scale = 0.08838834764831845f;

    #pragma unroll
    for (int it = 0; it < 16; it++) {
        int idx = tid + it * 256;
        int i = idx >> 6, j = idx & 63;
        const float* q = base + (long)i * 3 * ND + h * NHD;
        const float* k = base + (long)j * 3 * ND + ND + h * NHD;
        float acc = 0.f;
        #pragma unroll 8
        for (int d = 0; d < NHD; d++) acc += q[d] * k[d];
        sc[i*64 + j] = acc * scale;
    }
    __syncthreads();

    int warp = tid >> 5, lane = tid & 31;
    for (int r = warp; r < 64; r += 8) {
        float v0 = sc[r*64 + lane], v1 = sc[r*64 + lane + 32];
        float m = fmaxf(v0, v1);
        #pragma unroll
        for (int o = 16; o > 0; o >>= 1) m = fmaxf(m, __shfl_xor_sync(0xffffffffu, m, o));
        v0 = expf(v0 - m); v1 = expf(v1 - m);
        float s = v0 + v1;
        #pragma unroll
        for (int o = 16; o > 0; o >>= 1) s += __shfl_xor_sync(0xffffffffu, s, o);
        float inv = 1.0f / s;
        sc[r*64 + lane] = v0 * inv; sc[r*64 + lane + 32] = v1 * inv;
    }
    __syncthreads();

    #pragma unroll
    for (int it = 0; it < 32; it++) {
        int idx = tid + it * 256;
        int i = idx >> 7, d = idx & 127;
        const float* v = base + 2 * ND + h * NHD + d;
        float acc = 0.f;
        #pragma unroll 8
        for (int j = 0; j < 64; j++) acc += sc[i*64 + j] * v[(long)j * 3 * ND];
        long off = ((long)b * NA + i) * ND + h * NHD + d;
        __nv_bfloat16 hh = __float2bfloat16(acc);
        g_ctxhi[off] = hh;
        g_ctxlo[off] = __float2bfloat16(acc - __bfloat162float(hh));
    }
}

__device__ __forceinline__ float blockReduceSum(float v)
{
    __shared__ float sh[9];
    __syncthreads();
    int lane = threadIdx.x & 31, warp = threadIdx.x >> 5;
    #pragma unroll
    for (int o = 16; o > 0; o >>= 1) v += __shfl_xor_sync(0xffffffffu, v, o);
    if (lane == 0) sh[warp] = v;
    __syncthreads();
    if (warp == 0) {
        float t = (lane < 8) ? sh[lane] : 0.f;
        #pragma unroll
        for (int o = 4; o > 0; o >>= 1) t += __shfl_xor_sync(0xffffffffu, t, o);
        if (lane == 0) sh[8] = t;
    }
    __syncthreads();
    return sh[8];
}

// ---- out = LayerNorm(X + Y) * g + b ; optional bf16 split side-output ----
__global__ void add_ln(const float* __restrict__ X, const float* __restrict__ Y,
                       const float* __restrict__ gam, const float* __restrict__ bet,
                       float* __restrict__ out,
                       __nv_bfloat16* __restrict__ ohi, __nv_bfloat16* __restrict__ olo)
{
    long row = blockIdx.x;
    int tid = threadIdx.x;
    float vals[4];
    float s = 0.f;
    #pragma unroll
    for (int i = 0; i < 4; i++) {
        int d = tid + i * 256;
        float v = X[row * ND + d] + Y[row * ND + d];
        vals[i] = v; s += v;
    }
    float mean = blockReduceSum(s) * (1.0f / ND);
    float vs = 0.f;
    #pragma unroll
    for (int i = 0; i < 4; i++) { float t = vals[i] - mean; vs += t * t; }
    float var = blockReduceSum(vs) * (1.0f / ND);
    float inv = rsqrtf(var + 1e-5f);
    #pragma unroll
    for (int i = 0; i < 4; i++) {
        int d = tid + i * 256;
        float o = (vals[i] - mean) * inv * gam[d] + bet[d];
        out[row * ND + d] = o;
        if (ohi) {
            __nv_bfloat16 h = __float2bfloat16(o);
            ohi[row * ND + d] = h;
            olo[row * ND + d] = __float2bfloat16(o - __bfloat162float(h));
        }
    }
}

// ============================================================
extern "C" void kernel_launch(void* const* d_in, const int* in_sizes, int n_in,
                              void* d_out, int out_size)
{
    const float* x     = (const float*)d_in[0];
    const float* efas  = (const float*)d_in[1];
    const float* ep_w  = (const float*)d_in[2];
    const float* ep_b  = (const float*)d_in[3];
    const float* rm_w1 = (const float*)d_in[5];
    const float* rm_b1 = (const float*)d_in[6];
    const float* rm_w2 = (const float*)d_in[7];
    const float* rm_b2 = (const float*)d_in[8];
    const float* in_w  = (const float*)d_in[9];
    const float* in_b  = (const float*)d_in[10];
    const float* ow    = (const float*)d_in[11];
    const float* ob    = (const float*)d_in[12];
    const float* fw1   = (const float*)d_in[13];
    const float* fb1   = (const float*)d_in[14];
    const float* fw2   = (const float*)d_in[15];
    const float* fb2   = (const float*)d_in[16];
    const float* l1g   = (const float*)d_in[17];
    const float* l1b   = (const float*)d_in[18];
    const float* l2g   = (const float*)d_in[19];
    const float* l2b   = (const float*)d_in[20];
    float* out = (float*)d_out;

    float *p_logits, *p_rw, *p_qkv, *p_mixed, *p_h, *p_f, *p_u, *p_bv, *p_b2p;
    __nv_bfloat16 *p_xhi, *p_xlo, *p_w1hi, *p_w1lo, *p_hidhi, *p_hidlo,
                  *p_w2phi, *p_w2plo, *p_rwThi, *p_rwTlo, *p_anchhi, *p_anchlo,
                  *p_inhi, *p_inlo, *p_ctxhi, *p_ctxlo, *p_owhi, *p_owlo,
                  *p_hhi, *p_hlo, *p_f1hi, *p_f1lo, *p_f2hi, *p_f2lo, *p_thi, *p_tlo;
    cudaGetSymbolAddress((void**)&p_logits,  g_logits);
    cudaGetSymbolAddress((void**)&p_rw,      g_rw);
    cudaGetSymbolAddress((void**)&p_qkv,     g_qkv);
    cudaGetSymbolAddress((void**)&p_mixed,   g_mixed);
    cudaGetSymbolAddress((void**)&p_h,       g_h);
    cudaGetSymbolAddress((void**)&p_f,       g_f);
    cudaGetSymbolAddress((void**)&p_u,       g_uvec);
    cudaGetSymbolAddress((void**)&p_bv,      g_bvec);
    cudaGetSymbolAddress((void**)&p_b2p,     g_b2p);
    cudaGetSymbolAddress((void**)&p_xhi,     g_xhi);
    cudaGetSymbolAddress((void**)&p_xlo,     g_xlo);
    cudaGetSymbolAddress((void**)&p_w1hi,    g_w1hi);
    cudaGetSymbolAddress((void**)&p_w1lo,    g_w1lo);
    cudaGetSymbolAddress((void**)&p_hidhi,   g_hidhi);
    cudaGetSymbolAddress((void**)&p_hidlo,   g_hidlo);
    cudaGetSymbolAddress((void**)&p_w2phi,   g_w2phi);
    cudaGetSymbolAddress((void**)&p_w2plo,   g_w2plo);
    cudaGetSymbolAddress((void**)&p_rwThi,   g_rwThi);
    cudaGetSymbolAddress((void**)&p_rwTlo,   g_rwTlo);
    cudaGetSymbolAddress((void**)&p_anchhi,  g_anchhi);
    cudaGetSymbolAddress((void**)&p_anchlo,  g_anchlo);
    cudaGetSymbolAddress((void**)&p_inhi,    g_inhi);
    cudaGetSymbolAddress((void**)&p_inlo,    g_inlo);
    cudaGetSymbolAddress((void**)&p_ctxhi,   g_ctxhi);
    cudaGetSymbolAddress((void**)&p_ctxlo,   g_ctxlo);
    cudaGetSymbolAddress((void**)&p_owhi,    g_owhi);
    cudaGetSymbolAddress((void**)&p_owlo,    g_owlo);
    cudaGetSymbolAddress((void**)&p_hhi,     g_hhi);
    cudaGetSymbolAddress((void**)&p_hlo,     g_hlo);
    cudaGetSymbolAddress((void**)&p_f1hi,    g_f1hi);
    cudaGetSymbolAddress((void**)&p_f1lo,    g_f1lo);
    cudaGetSymbolAddress((void**)&p_f2hi,    g_f2hi);
    cudaGetSymbolAddress((void**)&p_f2lo,    g_f2lo);
    cudaGetSymbolAddress((void**)&p_thi,     g_thi);
    cudaGetSymbolAddress((void**)&p_tlo,     g_tlo);

    static bool attr_set = false;
    if (!attr_set) {
        cudaFuncSetAttribute(gemm_v2<false>, cudaFuncAttributeMaxDynamicSharedMemorySize, V2_SMEM);
        cudaFuncSetAttribute(gemm_bf16s<true,true,true>,   cudaFuncAttributeMaxDynamicSharedMemorySize, BF_SMEM);
        cudaFuncSetAttribute(gemm_bf16s<true,true,false>,  cudaFuncAttributeMaxDynamicSharedMemorySize, BF_SMEM);
        cudaFuncSetAttribute(gemm_bf16s<false,false,false>,cudaFuncAttributeMaxDynamicSharedMemorySize, BF_SMEM);
        cudaFuncSetAttribute(gemm_bf16s64<true>, cudaFuncAttributeMaxDynamicSharedMemorySize, B64_SMEM);
        attr_set = true;
    }

    dim3 blk128(128);
    auto sl = [](long n) { return (unsigned)((n + 255) / 256); };

    // Launch order: hidden GEMM at index 3 (ncu profiles idx 3).
    prep_uv<<<4, 256>>>(rm_w1, rm_b1, ep_w, ep_b);                                  // 0
    split_bf<<<sl((long)NBS*ND), 256>>>(x, p_xhi, p_xlo, (long)NBS*ND);             // 1
    split_bf<<<sl((long)ND*ND), 256>>>(rm_w1, p_w1hi, p_w1lo, (long)ND*ND);         // 2

    // 3) hidden = relu(x@W1x + efas*u + bvec)  bf16s, split out  ← ncu target
    gemm_bf16s<true,true,true><<<dim3(ND/128, NBS/128), blk128, BF_SMEM>>>(
        p_xhi, p_xlo, p_w1hi, p_w1lo, p_bv, efas, p_u,
        nullptr, p_hidhi, p_hidlo, NBS, ND, ND);

    pad_w2_bf<<<512, 256>>>(rm_w2, rm_b2);
    split_bf<<<sl((long)ND*3*ND), 256>>>(in_w, p_inhi, p_inlo, (long)ND*3*ND);
    split_bf<<<sl((long)ND*ND), 256>>>(ow, p_owhi, p_owlo, (long)ND*ND);
    split_bf<<<sl((long)ND*4*ND), 256>>>(fw1, p_f1hi, p_f1lo, (long)ND*4*ND);
    split_bf<<<sl((long)4*ND*ND), 256>>>(fw2, p_f2hi, p_f2lo, (long)4*ND*ND);

    // logits(padded N=128) = hidden @ w2p + b2p   bf16s
    gemm_bf16s<false,false,false><<<dim3(1, NBS/128), blk128, BF_SMEM>>>(
        p_hidhi, p_hidlo, p_w2phi, p_w2plo, p_b2p, nullptr, nullptr,
        p_logits, nullptr, nullptr, NBS, 128, ND);

    softmax64<<<NBS/8, 256>>>();

    // anchors[b] = rwT[b] @ x[b]   bf16s64, split out  [64,4096]x[4096,1024]
    gemm_bf16s64<true><<<dim3(ND/128, 1, NB), blk128, B64_SMEM>>>(
        p_rwThi, p_rwTlo, p_xhi, p_xlo,
        nullptr, p_anchhi, p_anchlo,
        ND, NS, (long)NA*NS, (long)NS*ND, (long)NA*ND);

    // qkv = anchors @ in_w + in_b   bf16s           [512,1024]x[1024,3072]
    gemm_bf16s<false,false,false><<<dim3(3*ND/128, NB*NA/128), blk128, BF_SMEM>>>(
        p_anchhi, p_anchlo, p_inhi, p_inlo, in_b, nullptr, nullptr,
        p_qkv, nullptr, nullptr, NB*NA, 3*ND, ND);

    attn_kernel<<<dim3(NH, NB), 256>>>();

    // mixed = ctx @ ow + ob         bf16s           [512,1024]x[1024,1024]
    gemm_bf16s<false,false,false><<<dim3(ND/128, NB*NA/128), blk128, BF_SMEM>>>(
        p_ctxhi, p_ctxlo, p_owhi, p_owlo, ob, nullptr, nullptr,
        p_mixed, nullptr, nullptr, NB*NA, ND, ND);

    // token_updates[b] = rw[b] @ mixed[b]   tf32, batched (K=64)
    gemm_v2<false><<<dim3(ND/128, NS/128, NB), blk128, V2_SMEM>>>(
        p_rw, p_mixed, nullptr, nullptr, nullptr, p_f, NS, ND, NA,
        NA, ND, ND, (long)NS*NA, (long)NA*ND, (long)NS*ND);

    // h = LN1(x + token_updates)  (fp32 for LN2 + bf16 hi/lo for ffn1)
    add_ln<<<NBS, 256>>>(x, p_f, l1g, l1b, p_h, p_hhi, p_hlo);

    // t = relu(h @ fw1 + fb1)   bf16s, split out  [32768,1024]x[1024,4096]
    gemm_bf16s<true,true,false><<<dim3(4*ND/128, NBS/128), blk128, BF_SMEM>>>(
        p_hhi, p_hlo, p_f1hi, p_f1lo, fb1, nullptr, nullptr,
        nullptr, p_thi, p_tlo, NBS, 4*ND, ND);

    // f = t @ fw2 + fb2         bf16s            [32768,4096]x[4096,1024]
    gemm_bf16s<false,false,false><<<dim3(ND/128, NBS/128), blk128, BF_SMEM>>>(
        p_thi, p_tlo, p_f2hi, p_f2lo, fb2, nullptr, nullptr,
        p_f, nullptr, nullptr, NBS, ND, 4*ND);

    // out = LN2(h + f)  (full precision)
    add_ln<<<NBS, 256>>>(p_h, p_f, l2g, l2b, out, nullptr, nullptr);
}